// round 2
// baseline (speedup 1.0000x reference)
#include <cuda_runtime.h>
#include <math.h>

#define NN     2048
#define EE     16384
#define BBATCH 32
#define TP2    61
#define DD     128
#define C3N    32

// ---------------- scratch ----------------
__device__ float g_h0[NN * TP2 * C3N];
__device__ float g_s0[NN * TP2 * C3N];
__device__ float g_h1[NN * TP2 * DD];
__device__ float g_s1[NN * TP2 * DD];
__device__ float g_h2[NN * TP2 * DD];
__device__ float g_contrib[NN * 4];
__device__ float g_dinv[NN];
__device__ int   g_cnt[NN];
__device__ int   g_off[NN + 1];
__device__ int   g_cur[NN];
__device__ int   g_col[EE];

// ---------------- graph prep ----------------
__global__ void zero_cnt_kernel() {
    int i = blockIdx.x * blockDim.x + threadIdx.x;
    if (i < NN) g_cnt[i] = 0;
}

__global__ void count_kernel(const int* __restrict__ ei) {
    int e = blockIdx.x * blockDim.x + threadIdx.x;
    if (e < EE) atomicAdd(&g_cnt[ei[EE + e]], 1);
}

__global__ void scan_kernel() {
    __shared__ int csum[256];
    const int tid = threadIdx.x;
    const int base = tid * 8;
    int local[8];
    int s = 0;
#pragma unroll
    for (int i = 0; i < 8; i++) { local[i] = s; s += g_cnt[base + i]; }
    csum[tid] = s;
    __syncthreads();
    for (int ofs = 1; ofs < 256; ofs <<= 1) {
        int v = (tid >= ofs) ? csum[tid - ofs] : 0;
        __syncthreads();
        csum[tid] += v;
        __syncthreads();
    }
    int pre = (tid == 0) ? 0 : csum[tid - 1];
#pragma unroll
    for (int i = 0; i < 8; i++) {
        int o = pre + local[i];
        g_off[base + i] = o;
        g_cur[base + i] = o;
        g_dinv[base + i] = rsqrtf((float)(g_cnt[base + i] + 1));
    }
    if (tid == 255) g_off[NN] = pre + s;
}

__global__ void fill_kernel(const int* __restrict__ ei) {
    int e = blockIdx.x * blockDim.x + threadIdx.x;
    if (e < EE) {
        int src = ei[e];
        int dst = ei[EE + e];
        int p = atomicAdd(&g_cur[dst], 1);
        g_col[p] = src;
    }
}

// ---------------- fused CNN + pos-MLP (one block per node) ----------------
// smem floats: sxp[0,1048) h1[1048,9248) u1[9248,17416)
//              h2 reuses [0,4048)   u2 reuses [4048,8032)
//              weights/misc [17416,23296)
#define CONV_SMEM_BYTES (23296 * 4)

__global__ __launch_bounds__(256) void conv_kernel(
    const float* __restrict__ x,   const float* __restrict__ pos,
    const float* __restrict__ c1w, const float* __restrict__ c1b,
    const float* __restrict__ g1,  const float* __restrict__ b1,
    const float* __restrict__ c2w, const float* __restrict__ c2b,
    const float* __restrict__ g2,  const float* __restrict__ b2,
    const float* __restrict__ c3w, const float* __restrict__ c3b,
    const float* __restrict__ g3,  const float* __restrict__ b3,
    const float* __restrict__ pw1, const float* __restrict__ pb1,
    const float* __restrict__ pw2, const float* __restrict__ pb2,
    float* __restrict__ out)
{
    extern __shared__ float sm[];
    float* sxp = sm;
    float* h1  = sm + 1048;
    float* u1  = sm + 9248;
    float* h2  = sm;
    float* u2  = sm + 4048;
    float* w1s = sm + 17416;     // 200
    float* w2t = sm + 17616;     // 1920   [ci*15+k][c2]
    float* w3t = sm + 19536;     // 3584   [ci*7+k][c3]
    float* s1v = sm + 23120;
    float* B1v = sm + 23128;
    float* s2v = sm + 23136;
    float* B2v = sm + 23152;
    float* s3v = sm + 23168;
    float* B3v = sm + 23200;
    float* peS = sm + 23232;
    float* hidS= sm + 23264;

    const int n = blockIdx.x;
    const int tid = threadIdx.x;
    const float rs = rsqrtf(1.0f + 1e-5f);

    for (int i = tid; i < 200; i += 256) w1s[i] = c1w[i];
    for (int i = tid; i < 1920; i += 256) { int c2 = i & 15, r = i >> 4; w2t[i] = c2w[c2 * 120 + r]; }
    for (int i = tid; i < 3584; i += 256) { int c3 = i & 31, r = i >> 5; w3t[i] = c3w[c3 * 112 + r]; }
    if (tid < 8) {
        float s = g1[tid] * rs; s1v[tid] = s; B1v[tid] = c1b[tid] * s + b1[tid];
    } else if (tid >= 32 && tid < 48) {
        int c = tid - 32; float s = g2[c] * rs; s2v[c] = s; B2v[c] = c2b[c] * s + b2[c];
    } else if (tid >= 64 && tid < 96) {
        int c = tid - 64; float s = g3[c] * rs; s3v[c] = s; B3v[c] = c3b[c] * s + b3[c];
    }
    if (tid >= 128 && tid < 160) {
        int c = tid - 128;
        float p0 = pos[n * 3 + 0], p1 = pos[n * 3 + 1], p2 = pos[n * 3 + 2];
        float h = p0 * pw1[c] + p1 * pw1[32 + c] + p2 * pw1[64 + c] + pb1[c];
        hidS[c] = fmaxf(h, 0.f);
    }
    for (int i = tid; i < 1024; i += 256) sxp[12 + i] = x[(size_t)n * 1024 + i];
    if (tid < 12) { sxp[tid] = 0.f; sxp[1036 + tid] = 0.f; }
    __syncthreads();

    if (tid < 32) {                       // pos-MLP layer 2
        float s = pb2[tid];
#pragma unroll
        for (int j = 0; j < 32; j++) s += hidS[j] * pw2[j * 32 + tid];
        peS[tid] = s;
    }

    // conv1 (1->8, K=25, pad 12) + BN + relu
    {
        const int c0 = tid & 3, tg = tid >> 2;
        float accA[16], accB[16];
#pragma unroll
        for (int it = 0; it < 16; it++) { accA[it] = 0.f; accB[it] = 0.f; }
#pragma unroll
        for (int k = 0; k < 25; k++) {
            float wA = w1s[c0 * 25 + k];
            float wB = w1s[(c0 + 4) * 25 + k];
#pragma unroll
            for (int it = 0; it < 16; it++) {
                float u = sxp[tg + 64 * it + k];
                accA[it] += wA * u;
                accB[it] += wB * u;
            }
        }
        float sA = s1v[c0], BA = B1v[c0];
        float sB = s1v[c0 + 4], BBc = B1v[c0 + 4];
#pragma unroll
        for (int it = 0; it < 16; it++) {
            int t = tg + 64 * it;
            h1[c0 * 1025 + t]       = fmaxf(accA[it] * sA + BA, 0.f);
            h1[(c0 + 4) * 1025 + t] = fmaxf(accB[it] * sB + BBc, 0.f);
        }
    }
    __syncthreads();

    for (int ci = 0; ci < 8; ci++)        // u1 = 4-window mean of h1
        for (int j = tid; j < 1019; j += 256) {
            const float* hr = h1 + ci * 1025 + j;
            u1[ci * 1021 + j] = 0.25f * (hr[0] + hr[1] + hr[2] + hr[3]);
        }
    __syncthreads();

    // conv2 (8->16, K=15) fused with pool4 + BN + relu
    {
        const int c2h = tid & 7, tpb = tid >> 3;
        float accA[8], accB[8];
#pragma unroll
        for (int it = 0; it < 8; it++) { accA[it] = 0.f; accB[it] = 0.f; }
        for (int ci = 0; ci < 8; ci++) {
            float wA[15], wB[15];
#pragma unroll
            for (int k = 0; k < 15; k++) {
                wA[k] = w2t[(ci * 15 + k) * 16 + c2h];
                wB[k] = w2t[(ci * 15 + k) * 16 + c2h + 8];
            }
            const float* ub = u1 + ci * 1021;
#pragma unroll
            for (int k = 0; k < 15; k++) {
#pragma unroll
                for (int it = 0; it < 8; it++) {
                    int tp = tpb + 32 * it;
                    if (tp < 252) {
                        float u = ub[4 * tp + k];
                        accA[it] += wA[k] * u;
                        accB[it] += wB[k] * u;
                    }
                }
            }
        }
        float sA = s2v[c2h], BA = B2v[c2h];
        float sB = s2v[c2h + 8], BBc = B2v[c2h + 8];
#pragma unroll
        for (int it = 0; it < 8; it++) {
            int tp = tpb + 32 * it;
            if (tp < 252) {
                h2[c2h * 253 + tp]       = fmaxf(accA[it] * sA + BA, 0.f);
                h2[(c2h + 8) * 253 + tp] = fmaxf(accB[it] * sB + BBc, 0.f);
            }
        }
    }
    __syncthreads();

    for (int ci = 0; ci < 16; ci++)       // u2 = 4-window mean of h2
        for (int j = tid; j < 247; j += 256) {
            const float* hr = h2 + ci * 253 + j;
            u2[ci * 249 + j] = 0.25f * (hr[0] + hr[1] + hr[2] + hr[3]);
        }
    __syncthreads();

    // conv3 (16->32, K=7) fused with pool4 + BN + relu + pe, write (n,t,c)
    {
        const int c3h = tid & 15, tpg = tid >> 4;
        float accA[4], accB[4];
#pragma unroll
        for (int it = 0; it < 4; it++) { accA[it] = 0.f; accB[it] = 0.f; }
        for (int ci = 0; ci < 16; ci++) {
            float wA[7], wB[7];
#pragma unroll
            for (int k = 0; k < 7; k++) {
                wA[k] = w3t[(ci * 7 + k) * 32 + c3h];
                wB[k] = w3t[(ci * 7 + k) * 32 + c3h + 16];
            }
            const float* ub = u2 + ci * 249;
#pragma unroll
            for (int k = 0; k < 7; k++) {
#pragma unroll
                for (int it = 0; it < 4; it++) {
                    int tp = tpg + 16 * it;
                    if (tp < 61) {
                        float u = ub[4 * tp + k];
                        accA[it] += wA[k] * u;
                        accB[it] += wB[k] * u;
                    }
                }
            }
        }
        float sA = s3v[c3h], BA = B3v[c3h];
        float sB = s3v[c3h + 16], BBc = B3v[c3h + 16];
        float peA = peS[c3h], peB = peS[c3h + 16];
#pragma unroll
        for (int it = 0; it < 4; it++) {
            int tp = tpg + 16 * it;
            if (tp < 61) {
                size_t base = ((size_t)n * 61 + tp) * 32;
                out[base + c3h]      = fmaxf(accA[it] * sA + BA, 0.f) + peA;
                out[base + c3h + 16] = fmaxf(accB[it] * sB + BBc, 0.f) + peB;
            }
        }
    }
}

// ---------------- GCN neighbor aggregation (aggregate-before-GEMM) ----------------
template <int C>
__global__ __launch_bounds__(256) void agg_kernel(const float* __restrict__ h,
                                                  float* __restrict__ s)
{
    constexpr int V = TP2 * C;
    constexpr int VPT = (V + 255) / 256;
    const int n = blockIdx.x, tid = threadIdx.x;
    const float dvn = g_dinv[n];
    const float* hn = h + (size_t)n * V;
    float acc[VPT];
#pragma unroll
    for (int v = 0; v < VPT; v++) {
        int i = tid + v * 256;
        acc[v] = (i < V) ? hn[i] * dvn : 0.f;
    }
    const int jb = g_off[n], je = g_off[n + 1];
    for (int j = jb; j < je; j++) {
        const int src = g_col[j];
        const float dv = g_dinv[src];
        const float* hs = h + (size_t)src * V;
#pragma unroll
        for (int v = 0; v < VPT; v++) {
            int i = tid + v * 256;
            if (i < V) acc[v] += hs[i] * dv;
        }
    }
    float* sn = s + (size_t)n * V;
#pragma unroll
    for (int v = 0; v < VPT; v++) {
        int i = tid + v * 256;
        if (i < V) sn[i] = acc[v];
    }
}

// ---------------- GEMM: out = relu((A @ W) * dinv[row/61] + bias) ----------------
template <int K>
__global__ __launch_bounds__(256) void gemm_kernel(
    const float* __restrict__ A, const float* __restrict__ W,
    const float* __restrict__ bias, float* __restrict__ out)
{
    extern __shared__ float sgm[];
    float* ws = sgm;                 // K*128
    float* as = sgm + K * 128;       // 64*(K+1)
    __shared__ float bs[128];
    const int tid = threadIdx.x;
    for (int i = tid; i < K * 128; i += 256) ws[i] = W[i];
    if (tid < 128) bs[tid] = bias[tid];
    const int row0 = blockIdx.x * 64;
    for (int i = tid; i < 64 * K; i += 256) {
        int r = i / K, c = i % K;
        as[r * (K + 1) + c] = A[(size_t)(row0 + r) * K + c];
    }
    __syncthreads();
    const int tc = tid & 15, tr = tid >> 4;
    float acc[4][8];
#pragma unroll
    for (int i = 0; i < 4; i++)
#pragma unroll
        for (int j = 0; j < 8; j++) acc[i][j] = 0.f;

#pragma unroll 8
    for (int k = 0; k < K; k++) {
        float a[4];
#pragma unroll
        for (int i = 0; i < 4; i++) a[i] = as[(tr * 4 + i) * (K + 1) + k];
        float b[8];
        *(float4*)&b[0] = *(const float4*)&ws[k * 128 + tc * 8];
        *(float4*)&b[4] = *(const float4*)&ws[k * 128 + tc * 8 + 4];
#pragma unroll
        for (int i = 0; i < 4; i++)
#pragma unroll
            for (int j = 0; j < 8; j++) acc[i][j] += a[i] * b[j];
    }
#pragma unroll
    for (int i = 0; i < 4; i++) {
        int r = row0 + tr * 4 + i;
        float dv = g_dinv[r / 61];
        float o[8];
#pragma unroll
        for (int j = 0; j < 8; j++) o[j] = fmaxf(acc[i][j] * dv + bs[tc * 8 + j], 0.f);
        *(float4*)&out[(size_t)r * 128 + tc * 8]     = *(float4*)&o[0];
        *(float4*)&out[(size_t)r * 128 + tc * 8 + 4] = *(float4*)&o[4];
    }
}

// ---------------- per-node dense contribution ----------------
__global__ __launch_bounds__(256) void contrib_kernel(
    const float* __restrict__ h, const float* __restrict__ dw)
{
    const int n = blockIdx.x, tid = threadIdx.x;
    const float* hn = h + (size_t)n * (TP2 * DD);
    float a0 = 0.f, a1 = 0.f, a2 = 0.f, a3 = 0.f;
    for (int e = tid; e < TP2 * DD; e += 256) {
        int t = e >> 7, d = e & 127;
        float v = hn[e];
        const float4 w = *(const float4*)&dw[(size_t)(d * 61 + t) * 4];
        a0 += v * w.x; a1 += v * w.y; a2 += v * w.z; a3 += v * w.w;
    }
    __shared__ float r0[256], r1[256], r2[256], r3[256];
    r0[tid] = a0; r1[tid] = a1; r2[tid] = a2; r3[tid] = a3;
    __syncthreads();
    for (int s = 128; s > 0; s >>= 1) {
        if (tid < s) {
            r0[tid] += r0[tid + s]; r1[tid] += r1[tid + s];
            r2[tid] += r2[tid + s]; r3[tid] += r3[tid + s];
        }
        __syncthreads();
    }
    if (tid == 0) {
        g_contrib[n * 4 + 0] = r0[0];
        g_contrib[n * 4 + 1] = r1[0];
        g_contrib[n * 4 + 2] = r2[0];
        g_contrib[n * 4 + 3] = r3[0];
    }
}

// ---------------- batch pooling + bias + log_softmax ----------------
__global__ __launch_bounds__(256) void final_kernel(
    const int* __restrict__ batch, const float* __restrict__ db,
    float* __restrict__ out)
{
    const int b = blockIdx.x, tid = threadIdx.x;
    float a0 = 0.f, a1 = 0.f, a2 = 0.f, a3 = 0.f;
    int c = 0;
    for (int n = tid; n < NN; n += 256) {
        if (batch[n] == b) {
            const float4 v = *(const float4*)&g_contrib[n * 4];
            a0 += v.x; a1 += v.y; a2 += v.z; a3 += v.w;
            c++;
        }
    }
    __shared__ float r0[256], r1[256], r2[256], r3[256];
    __shared__ int rc[256];
    r0[tid] = a0; r1[tid] = a1; r2[tid] = a2; r3[tid] = a3; rc[tid] = c;
    __syncthreads();
    for (int s = 128; s > 0; s >>= 1) {
        if (tid < s) {
            r0[tid] += r0[tid + s]; r1[tid] += r1[tid + s];
            r2[tid] += r2[tid + s]; r3[tid] += r3[tid + s];
            rc[tid] += rc[tid + s];
        }
        __syncthreads();
    }
    if (tid == 0) {
        float cc = fmaxf((float)rc[0], 1.f);
        float l0 = r0[0] / cc + db[0];
        float l1 = r1[0] / cc + db[1];
        float l2 = r2[0] / cc + db[2];
        float l3 = r3[0] / cc + db[3];
        float m = fmaxf(fmaxf(l0, l1), fmaxf(l2, l3));
        float sum = expf(l0 - m) + expf(l1 - m) + expf(l2 - m) + expf(l3 - m);
        float ls = logf(sum);
        out[b * 4 + 0] = l0 - m - ls;
        out[b * 4 + 1] = l1 - m - ls;
        out[b * 4 + 2] = l2 - m - ls;
        out[b * 4 + 3] = l3 - m - ls;
    }
}

// ---------------- launch ----------------
extern "C" void kernel_launch(void* const* d_in, const int* in_sizes, int n_in,
                              void* d_out, int out_size)
{
    const float* x   = (const float*)d_in[0];
    const float* pos = (const float*)d_in[1];
    const float* c1w = (const float*)d_in[2];
    const float* c1b = (const float*)d_in[3];
    const float* bg1 = (const float*)d_in[4];
    const float* bb1 = (const float*)d_in[5];
    const float* c2w = (const float*)d_in[6];
    const float* c2b = (const float*)d_in[7];
    const float* bg2 = (const float*)d_in[8];
    const float* bb2 = (const float*)d_in[9];
    const float* c3w = (const float*)d_in[10];
    const float* c3b = (const float*)d_in[11];
    const float* bg3 = (const float*)d_in[12];
    const float* bb3 = (const float*)d_in[13];
    const float* pw1 = (const float*)d_in[14];
    const float* pb1 = (const float*)d_in[15];
    const float* pw2 = (const float*)d_in[16];
    const float* pb2 = (const float*)d_in[17];
    const float* gw1 = (const float*)d_in[18];
    const float* gb1 = (const float*)d_in[19];
    const float* gw2 = (const float*)d_in[20];
    const float* gb2 = (const float*)d_in[21];
    const float* dw  = (const float*)d_in[22];
    const float* db  = (const float*)d_in[23];
    const int*   ei  = (const int*)d_in[24];
    const int*   bat = (const int*)d_in[25];
    float* out = (float*)d_out;

    cudaFuncSetAttribute(conv_kernel, cudaFuncAttributeMaxDynamicSharedMemorySize, CONV_SMEM_BYTES);
    cudaFuncSetAttribute(gemm_kernel<128>, cudaFuncAttributeMaxDynamicSharedMemorySize,
                         (128 * 128 + 64 * 129) * 4);

    float *h0, *s0, *h1, *s1, *h2;
    cudaGetSymbolAddress((void**)&h0, g_h0);
    cudaGetSymbolAddress((void**)&s0, g_s0);
    cudaGetSymbolAddress((void**)&h1, g_h1);
    cudaGetSymbolAddress((void**)&s1, g_s1);
    cudaGetSymbolAddress((void**)&h2, g_h2);

    zero_cnt_kernel<<<8, 256>>>();
    count_kernel<<<64, 256>>>(ei);
    scan_kernel<<<1, 256>>>();
    fill_kernel<<<64, 256>>>(ei);

    conv_kernel<<<NN, 256, CONV_SMEM_BYTES>>>(
        x, pos, c1w, c1b, bg1, bb1, c2w, c2b, bg2, bb2,
        c3w, c3b, bg3, bb3, pw1, pb1, pw2, pb2, h0);

    agg_kernel<32><<<NN, 256>>>(h0, s0);
    gemm_kernel<32><<<(NN * TP2) / 64, 256, (32 * 128 + 64 * 33) * 4>>>(s0, gw1, gb1, h1);

    agg_kernel<128><<<NN, 256>>>(h1, s1);
    gemm_kernel<128><<<(NN * TP2) / 64, 256, (128 * 128 + 64 * 129) * 4>>>(s1, gw2, gb2, h2);

    contrib_kernel<<<NN, 256>>>(h2, dw);
    final_kernel<<<BBATCH, 256>>>(bat, db, out);
}

// round 3
// speedup vs baseline: 1.1195x; 1.1195x over previous
#include <cuda_runtime.h>
#include <math.h>
#include <mma.h>

using namespace nvcuda;

#define NN     2048
#define EE     16384
#define BBATCH 32
#define TP2    61
#define DD     128
#define C3N    32

// ---------------- scratch ----------------
__device__ float g_h0[NN * TP2 * C3N];
__device__ float g_s0[NN * TP2 * C3N];
__device__ float g_h1[NN * TP2 * DD];
__device__ float g_s1[NN * TP2 * DD];
__device__ float g_h2[NN * TP2 * DD];
__device__ float g_contrib[NN * 4];
__device__ float g_dinv[NN];
__device__ int   g_cnt[NN];
__device__ int   g_off[NN + 1];
__device__ int   g_cur[NN];
__device__ int   g_col[EE];

// ---------------- graph prep ----------------
__global__ void zero_cnt_kernel() {
    int i = blockIdx.x * blockDim.x + threadIdx.x;
    if (i < NN) g_cnt[i] = 0;
}

__global__ void count_kernel(const int* __restrict__ ei) {
    int e = blockIdx.x * blockDim.x + threadIdx.x;
    if (e < EE) atomicAdd(&g_cnt[ei[EE + e]], 1);
}

__global__ void scan_kernel() {
    __shared__ int csum[256];
    const int tid = threadIdx.x;
    const int base = tid * 8;
    int local[8];
    int s = 0;
#pragma unroll
    for (int i = 0; i < 8; i++) { local[i] = s; s += g_cnt[base + i]; }
    csum[tid] = s;
    __syncthreads();
    for (int ofs = 1; ofs < 256; ofs <<= 1) {
        int v = (tid >= ofs) ? csum[tid - ofs] : 0;
        __syncthreads();
        csum[tid] += v;
        __syncthreads();
    }
    int pre = (tid == 0) ? 0 : csum[tid - 1];
#pragma unroll
    for (int i = 0; i < 8; i++) {
        int o = pre + local[i];
        g_off[base + i] = o;
        g_cur[base + i] = o;
        g_dinv[base + i] = rsqrtf((float)(g_cnt[base + i] + 1));
    }
    if (tid == 255) g_off[NN] = pre + s;
}

__global__ void fill_kernel(const int* __restrict__ ei) {
    int e = blockIdx.x * blockDim.x + threadIdx.x;
    if (e < EE) {
        int src = ei[e];
        int dst = ei[EE + e];
        int p = atomicAdd(&g_cur[dst], 1);
        g_col[p] = src;
    }
}

// ---------------- fused CNN + pos-MLP (one block per node) ----------------
#define CONV_SMEM_BYTES (23296 * 4)

__global__ __launch_bounds__(256) void conv_kernel(
    const float* __restrict__ x,   const float* __restrict__ pos,
    const float* __restrict__ c1w, const float* __restrict__ c1b,
    const float* __restrict__ g1,  const float* __restrict__ b1,
    const float* __restrict__ c2w, const float* __restrict__ c2b,
    const float* __restrict__ g2,  const float* __restrict__ b2,
    const float* __restrict__ c3w, const float* __restrict__ c3b,
    const float* __restrict__ g3,  const float* __restrict__ b3,
    const float* __restrict__ pw1, const float* __restrict__ pb1,
    const float* __restrict__ pw2, const float* __restrict__ pb2,
    float* __restrict__ out)
{
    extern __shared__ float sm[];
    float* sxp = sm;
    float* h1  = sm + 1048;
    float* u1  = sm + 9248;
    float* h2  = sm;
    float* u2  = sm + 4048;
    float* w1s = sm + 17416;     // 200
    float* w2t = sm + 17616;     // 1920   [ci*15+k][c2]
    float* w3t = sm + 19536;     // 3584   [ci*7+k][c3]
    float* s1v = sm + 23120;
    float* B1v = sm + 23128;
    float* s2v = sm + 23136;
    float* B2v = sm + 23152;
    float* s3v = sm + 23168;
    float* B3v = sm + 23200;
    float* peS = sm + 23232;
    float* hidS= sm + 23264;

    const int n = blockIdx.x;
    const int tid = threadIdx.x;
    const float rs = rsqrtf(1.0f + 1e-5f);

    for (int i = tid; i < 200; i += 256) w1s[i] = c1w[i];
    for (int i = tid; i < 1920; i += 256) { int c2 = i & 15, r = i >> 4; w2t[i] = c2w[c2 * 120 + r]; }
    for (int i = tid; i < 3584; i += 256) { int c3 = i & 31, r = i >> 5; w3t[i] = c3w[c3 * 112 + r]; }
    if (tid < 8) {
        float s = g1[tid] * rs; s1v[tid] = s; B1v[tid] = c1b[tid] * s + b1[tid];
    } else if (tid >= 32 && tid < 48) {
        int c = tid - 32; float s = g2[c] * rs; s2v[c] = s; B2v[c] = c2b[c] * s + b2[c];
    } else if (tid >= 64 && tid < 96) {
        int c = tid - 64; float s = g3[c] * rs; s3v[c] = s; B3v[c] = c3b[c] * s + b3[c];
    }
    if (tid >= 128 && tid < 160) {
        int c = tid - 128;
        float p0 = pos[n * 3 + 0], p1 = pos[n * 3 + 1], p2 = pos[n * 3 + 2];
        float h = p0 * pw1[c] + p1 * pw1[32 + c] + p2 * pw1[64 + c] + pb1[c];
        hidS[c] = fmaxf(h, 0.f);
    }
    for (int i = tid; i < 1024; i += 256) sxp[12 + i] = x[(size_t)n * 1024 + i];
    if (tid < 12) { sxp[tid] = 0.f; sxp[1036 + tid] = 0.f; }
    __syncthreads();

    if (tid < 32) {                       // pos-MLP layer 2
        float s = pb2[tid];
#pragma unroll
        for (int j = 0; j < 32; j++) s += hidS[j] * pw2[j * 32 + tid];
        peS[tid] = s;
    }

    // conv1 (1->8, K=25, pad 12) + BN + relu
    {
        const int c0 = tid & 3, tg = tid >> 2;
        float accA[16], accB[16];
#pragma unroll
        for (int it = 0; it < 16; it++) { accA[it] = 0.f; accB[it] = 0.f; }
#pragma unroll
        for (int k = 0; k < 25; k++) {
            float wA = w1s[c0 * 25 + k];
            float wB = w1s[(c0 + 4) * 25 + k];
#pragma unroll
            for (int it = 0; it < 16; it++) {
                float u = sxp[tg + 64 * it + k];
                accA[it] += wA * u;
                accB[it] += wB * u;
            }
        }
        float sA = s1v[c0], BA = B1v[c0];
        float sB = s1v[c0 + 4], BBc = B1v[c0 + 4];
#pragma unroll
        for (int it = 0; it < 16; it++) {
            int t = tg + 64 * it;
            h1[c0 * 1025 + t]       = fmaxf(accA[it] * sA + BA, 0.f);
            h1[(c0 + 4) * 1025 + t] = fmaxf(accB[it] * sB + BBc, 0.f);
        }
    }
    __syncthreads();

    for (int ci = 0; ci < 8; ci++)        // u1 = 4-window mean of h1
        for (int j = tid; j < 1019; j += 256) {
            const float* hr = h1 + ci * 1025 + j;
            u1[ci * 1021 + j] = 0.25f * (hr[0] + hr[1] + hr[2] + hr[3]);
        }
    __syncthreads();

    // conv2 (8->16, K=15) fused with pool4 + BN + relu
    {
        const int c2h = tid & 7, tpb = tid >> 3;
        float accA[8], accB[8];
#pragma unroll
        for (int it = 0; it < 8; it++) { accA[it] = 0.f; accB[it] = 0.f; }
        for (int ci = 0; ci < 8; ci++) {
            float wA[15], wB[15];
#pragma unroll
            for (int k = 0; k < 15; k++) {
                wA[k] = w2t[(ci * 15 + k) * 16 + c2h];
                wB[k] = w2t[(ci * 15 + k) * 16 + c2h + 8];
            }
            const float* ub = u1 + ci * 1021;
#pragma unroll
            for (int k = 0; k < 15; k++) {
#pragma unroll
                for (int it = 0; it < 8; it++) {
                    int tp = tpb + 32 * it;
                    if (tp < 252) {
                        float u = ub[4 * tp + k];
                        accA[it] += wA[k] * u;
                        accB[it] += wB[k] * u;
                    }
                }
            }
        }
        float sA = s2v[c2h], BA = B2v[c2h];
        float sB = s2v[c2h + 8], BBc = B2v[c2h + 8];
#pragma unroll
        for (int it = 0; it < 8; it++) {
            int tp = tpb + 32 * it;
            if (tp < 252) {
                h2[c2h * 253 + tp]       = fmaxf(accA[it] * sA + BA, 0.f);
                h2[(c2h + 8) * 253 + tp] = fmaxf(accB[it] * sB + BBc, 0.f);
            }
        }
    }
    __syncthreads();

    for (int ci = 0; ci < 16; ci++)       // u2 = 4-window mean of h2
        for (int j = tid; j < 247; j += 256) {
            const float* hr = h2 + ci * 253 + j;
            u2[ci * 249 + j] = 0.25f * (hr[0] + hr[1] + hr[2] + hr[3]);
        }
    __syncthreads();

    // conv3 (16->32, K=7) fused with pool4 + BN + relu + pe, write (n,t,c)
    {
        const int c3h = tid & 15, tpg = tid >> 4;
        float accA[4], accB[4];
#pragma unroll
        for (int it = 0; it < 4; it++) { accA[it] = 0.f; accB[it] = 0.f; }
        for (int ci = 0; ci < 16; ci++) {
            float wA[7], wB[7];
#pragma unroll
            for (int k = 0; k < 7; k++) {
                wA[k] = w3t[(ci * 7 + k) * 32 + c3h];
                wB[k] = w3t[(ci * 7 + k) * 32 + c3h + 16];
            }
            const float* ub = u2 + ci * 249;
#pragma unroll
            for (int k = 0; k < 7; k++) {
#pragma unroll
                for (int it = 0; it < 4; it++) {
                    int tp = tpg + 16 * it;
                    if (tp < 61) {
                        float u = ub[4 * tp + k];
                        accA[it] += wA[k] * u;
                        accB[it] += wB[k] * u;
                    }
                }
            }
        }
        float sA = s3v[c3h], BA = B3v[c3h];
        float sB = s3v[c3h + 16], BBc = B3v[c3h + 16];
        float peA = peS[c3h], peB = peS[c3h + 16];
#pragma unroll
        for (int it = 0; it < 4; it++) {
            int tp = tpg + 16 * it;
            if (tp < 61) {
                size_t base = ((size_t)n * 61 + tp) * 32;
                out[base + c3h]      = fmaxf(accA[it] * sA + BA, 0.f) + peA;
                out[base + c3h + 16] = fmaxf(accB[it] * sB + BBc, 0.f) + peB;
            }
        }
    }
}

// ---------------- GCN aggregation (float4 gather) ----------------
template <int C>
__global__ __launch_bounds__(256) void agg_kernel(const float* __restrict__ h,
                                                  float* __restrict__ s)
{
    constexpr int V4 = TP2 * C / 4;          // 488 (C=32) / 1952 (C=128)
    constexpr int VPT = (V4 + 255) / 256;    // 2 / 8
    const int n = blockIdx.x, tid = threadIdx.x;
    const float dvn = g_dinv[n];
    const float4* hn = (const float4*)(h + (size_t)n * (TP2 * C));
    float4 acc[VPT];
#pragma unroll
    for (int v = 0; v < VPT; v++) {
        int i = tid + v * 256;
        if (i < V4) {
            float4 t = hn[i];
            acc[v] = make_float4(t.x * dvn, t.y * dvn, t.z * dvn, t.w * dvn);
        } else acc[v] = make_float4(0.f, 0.f, 0.f, 0.f);
    }
    const int jb = g_off[n], je = g_off[n + 1];
    for (int j = jb; j < je; j++) {
        const int src = g_col[j];
        const float dv = g_dinv[src];
        const float4* hs = (const float4*)(h + (size_t)src * (TP2 * C));
#pragma unroll
        for (int v = 0; v < VPT; v++) {
            int i = tid + v * 256;
            if (i < V4) {
                float4 t = hs[i];
                acc[v].x += t.x * dv; acc[v].y += t.y * dv;
                acc[v].z += t.z * dv; acc[v].w += t.w * dv;
            }
        }
    }
    float4* sn = (float4*)(s + (size_t)n * (TP2 * C));
#pragma unroll
    for (int v = 0; v < VPT; v++) {
        int i = tid + v * 256;
        if (i < V4) sn[i] = acc[v];
    }
}

// ---------------- tf32 tensor-core GEMM ----------------
// out[M,128] = relu((A[M,K] @ W[K,128]) * dinv[row/61] + bias)
// block tile 128x128, 8 warps (4 row x 2 col), warp tile 32x64, wmma m16n16k8 tf32
template <int K>
__global__ __launch_bounds__(256) void gemm_tc_kernel(
    const float* __restrict__ A, const float* __restrict__ W,
    const float* __restrict__ bias, float* __restrict__ out)
{
    constexpr int LDA = K + 4;               // 36 / 132, multiple of 4
    constexpr int LDW = 132;
    constexpr int LDC = 132;
    extern __shared__ float sg[];
    float* ws = sg;                           // K * 132
    float* as = sg + K * LDW;                 // 128 * LDA  (reused as C tile: 128*132)
    float* cs = as;
    __shared__ float bs[128];

    const int tid = threadIdx.x;
    const int wid = tid >> 5;
    const int wr = wid & 3;                   // warp row (0..3) -> 32 rows
    const int wc = wid >> 2;                  // warp col (0..1) -> 64 cols
    const int row0 = blockIdx.x * 128;

    if (tid < 128) bs[tid] = bias[tid];
    // load W (K x 128) into ws with stride 132
    for (int i = tid; i < K * 32; i += 256) { // float4 granularity: 128/4 = 32 per row
        int k = i >> 5, c4 = i & 31;
        float4 v = *(const float4*)&W[k * 128 + c4 * 4];
        *(float4*)&ws[k * LDW + c4 * 4] = v;
    }
    // load A tile (128 x K) into as with stride LDA
    for (int i = tid; i < 128 * (K / 4); i += 256) {
        int r = i / (K / 4), c4 = i % (K / 4);
        float4 v = *(const float4*)&A[(size_t)(row0 + r) * K + c4 * 4];
        *(float4*)&as[r * LDA + c4 * 4] = v;
    }
    __syncthreads();

    wmma::fragment<wmma::accumulator, 16, 16, 8, float> cf[2][4];
#pragma unroll
    for (int i = 0; i < 2; i++)
#pragma unroll
        for (int j = 0; j < 4; j++) wmma::fill_fragment(cf[i][j], 0.f);

#pragma unroll
    for (int k0 = 0; k0 < K; k0 += 8) {
        wmma::fragment<wmma::matrix_a, 16, 16, 8, wmma::precision::tf32, wmma::row_major> af[2];
#pragma unroll
        for (int i = 0; i < 2; i++) {
            wmma::load_matrix_sync(af[i], as + (wr * 32 + i * 16) * LDA + k0, LDA);
#pragma unroll
            for (int t = 0; t < af[i].num_elements; t++)
                af[i].x[t] = wmma::__float_to_tf32(af[i].x[t]);
        }
        wmma::fragment<wmma::matrix_b, 16, 16, 8, wmma::precision::tf32, wmma::row_major> bf[4];
#pragma unroll
        for (int j = 0; j < 4; j++) {
            wmma::load_matrix_sync(bf[j], ws + k0 * LDW + wc * 64 + j * 16, LDW);
#pragma unroll
            for (int t = 0; t < bf[j].num_elements; t++)
                bf[j].x[t] = wmma::__float_to_tf32(bf[j].x[t]);
        }
#pragma unroll
        for (int i = 0; i < 2; i++)
#pragma unroll
            for (int j = 0; j < 4; j++)
                wmma::mma_sync(cf[i][j], af[i], bf[j], cf[i][j]);
    }
    __syncthreads();   // as is dead; reuse as C tile
#pragma unroll
    for (int i = 0; i < 2; i++)
#pragma unroll
        for (int j = 0; j < 4; j++)
            wmma::store_matrix_sync(cs + (wr * 32 + i * 16) * LDC + wc * 64 + j * 16,
                                    cf[i][j], LDC, wmma::mem_row_major);
    __syncthreads();

    // epilogue: *dinv + bias, relu, coalesced store
    for (int idx = tid; idx < 128 * 128; idx += 256) {
        int r = idx >> 7, c = idx & 127;
        int row = row0 + r;
        float dv = g_dinv[row / 61];
        out[(size_t)row * 128 + c] = fmaxf(cs[r * LDC + c] * dv + bs[c], 0.f);
    }
}

// ---------------- per-node dense contribution ----------------
__global__ __launch_bounds__(256) void contrib_kernel(
    const float* __restrict__ h, const float* __restrict__ dw)
{
    const int n = blockIdx.x, tid = threadIdx.x;
    const float* hn = h + (size_t)n * (TP2 * DD);
    float a0 = 0.f, a1 = 0.f, a2 = 0.f, a3 = 0.f;
    for (int e = tid; e < TP2 * DD; e += 256) {
        int t = e >> 7, d = e & 127;
        float v = hn[e];
        const float4 w = *(const float4*)&dw[(size_t)(d * 61 + t) * 4];
        a0 += v * w.x; a1 += v * w.y; a2 += v * w.z; a3 += v * w.w;
    }
    __shared__ float r0[256], r1[256], r2[256], r3[256];
    r0[tid] = a0; r1[tid] = a1; r2[tid] = a2; r3[tid] = a3;
    __syncthreads();
    for (int s = 128; s > 0; s >>= 1) {
        if (tid < s) {
            r0[tid] += r0[tid + s]; r1[tid] += r1[tid + s];
            r2[tid] += r2[tid + s]; r3[tid] += r3[tid + s];
        }
        __syncthreads();
    }
    if (tid == 0) {
        g_contrib[n * 4 + 0] = r0[0];
        g_contrib[n * 4 + 1] = r1[0];
        g_contrib[n * 4 + 2] = r2[0];
        g_contrib[n * 4 + 3] = r3[0];
    }
}

// ---------------- batch pooling + bias + log_softmax ----------------
__global__ __launch_bounds__(256) void final_kernel(
    const int* __restrict__ batch, const float* __restrict__ db,
    float* __restrict__ out)
{
    const int b = blockIdx.x, tid = threadIdx.x;
    float a0 = 0.f, a1 = 0.f, a2 = 0.f, a3 = 0.f;
    int c = 0;
    for (int n = tid; n < NN; n += 256) {
        if (batch[n] == b) {
            const float4 v = *(const float4*)&g_contrib[n * 4];
            a0 += v.x; a1 += v.y; a2 += v.z; a3 += v.w;
            c++;
        }
    }
    __shared__ float r0[256], r1[256], r2[256], r3[256];
    __shared__ int rc[256];
    r0[tid] = a0; r1[tid] = a1; r2[tid] = a2; r3[tid] = a3; rc[tid] = c;
    __syncthreads();
    for (int s = 128; s > 0; s >>= 1) {
        if (tid < s) {
            r0[tid] += r0[tid + s]; r1[tid] += r1[tid + s];
            r2[tid] += r2[tid + s]; r3[tid] += r3[tid + s];
            rc[tid] += rc[tid + s];
        }
        __syncthreads();
    }
    if (tid == 0) {
        float cc = fmaxf((float)rc[0], 1.f);
        float l0 = r0[0] / cc + db[0];
        float l1 = r1[0] / cc + db[1];
        float l2 = r2[0] / cc + db[2];
        float l3 = r3[0] / cc + db[3];
        float m = fmaxf(fmaxf(l0, l1), fmaxf(l2, l3));
        float sum = expf(l0 - m) + expf(l1 - m) + expf(l2 - m) + expf(l3 - m);
        float ls = logf(sum);
        out[b * 4 + 0] = l0 - m - ls;
        out[b * 4 + 1] = l1 - m - ls;
        out[b * 4 + 2] = l2 - m - ls;
        out[b * 4 + 3] = l3 - m - ls;
    }
}

// ---------------- launch ----------------
extern "C" void kernel_launch(void* const* d_in, const int* in_sizes, int n_in,
                              void* d_out, int out_size)
{
    const float* x   = (const float*)d_in[0];
    const float* pos = (const float*)d_in[1];
    const float* c1w = (const float*)d_in[2];
    const float* c1b = (const float*)d_in[3];
    const float* bg1 = (const float*)d_in[4];
    const float* bb1 = (const float*)d_in[5];
    const float* c2w = (const float*)d_in[6];
    const float* c2b = (const float*)d_in[7];
    const float* bg2 = (const float*)d_in[8];
    const float* bb2 = (const float*)d_in[9];
    const float* c3w = (const float*)d_in[10];
    const float* c3b = (const float*)d_in[11];
    const float* bg3 = (const float*)d_in[12];
    const float* bb3 = (const float*)d_in[13];
    const float* pw1 = (const float*)d_in[14];
    const float* pb1 = (const float*)d_in[15];
    const float* pw2 = (const float*)d_in[16];
    const float* pb2 = (const float*)d_in[17];
    const float* gw1 = (const float*)d_in[18];
    const float* gb1 = (const float*)d_in[19];
    const float* gw2 = (const float*)d_in[20];
    const float* gb2 = (const float*)d_in[21];
    const float* dw  = (const float*)d_in[22];
    const float* db  = (const float*)d_in[23];
    const int*   ei  = (const int*)d_in[24];
    const int*   bat = (const int*)d_in[25];
    float* out = (float*)d_out;

    const int gemm32_smem  = (32 * 132 + 128 * 132) * 4;
    const int gemm128_smem = (128 * 132 + 128 * 132) * 4;

    cudaFuncSetAttribute(conv_kernel, cudaFuncAttributeMaxDynamicSharedMemorySize, CONV_SMEM_BYTES);
    cudaFuncSetAttribute(gemm_tc_kernel<32>,  cudaFuncAttributeMaxDynamicSharedMemorySize, gemm32_smem);
    cudaFuncSetAttribute(gemm_tc_kernel<128>, cudaFuncAttributeMaxDynamicSharedMemorySize, gemm128_smem);

    float *h0, *s0, *h1, *s1, *h2;
    cudaGetSymbolAddress((void**)&h0, g_h0);
    cudaGetSymbolAddress((void**)&s0, g_s0);
    cudaGetSymbolAddress((void**)&h1, g_h1);
    cudaGetSymbolAddress((void**)&s1, g_s1);
    cudaGetSymbolAddress((void**)&h2, g_h2);

    zero_cnt_kernel<<<8, 256>>>();
    count_kernel<<<64, 256>>>(ei);
    scan_kernel<<<1, 256>>>();
    fill_kernel<<<64, 256>>>(ei);

    conv_kernel<<<NN, 256, CONV_SMEM_BYTES>>>(
        x, pos, c1w, c1b, bg1, bb1, c2w, c2b, bg2, bb2,
        c3w, c3b, bg3, bb3, pw1, pb1, pw2, pb2, h0);

    agg_kernel<32><<<NN, 256>>>(h0, s0);
    gemm_tc_kernel<32><<<(NN * TP2) / 128, 256, gemm32_smem>>>(s0, gw1, gb1, h1);

    agg_kernel<128><<<NN, 256>>>(h1, s1);
    gemm_tc_kernel<128><<<(NN * TP2) / 128, 256, gemm128_smem>>>(s1, gw2, gb2, h2);

    contrib_kernel<<<NN, 256>>>(h2, dw);
    final_kernel<<<BBATCH, 256>>>(bat, db, out);
}

// round 4
// speedup vs baseline: 1.3086x; 1.1689x over previous
#include <cuda_runtime.h>
#include <math.h>
#include <mma.h>

using namespace nvcuda;

#define NN     2048
#define EE     16384
#define BBATCH 32
#define TP2    61
#define DD     128
#define C3N    32

typedef unsigned long long u64b;

__device__ __forceinline__ void fma2(u64b& d, u64b a, u64b b) {
    asm("fma.rn.f32x2 %0, %1, %2, %0;" : "+l"(d) : "l"(a), "l"(b));
}
__device__ __forceinline__ float hsum2(u64b v) {
    float lo, hi;
    asm("mov.b64 {%0,%1}, %2;" : "=f"(lo), "=f"(hi) : "l"(v));
    return lo + hi;
}

// ---------------- scratch ----------------
__device__ float g_h0[NN * TP2 * C3N];
__device__ float g_s0[NN * TP2 * C3N];
__device__ float g_h1[NN * TP2 * DD];
__device__ float g_s1[NN * TP2 * DD];
__device__ float g_h2[NN * TP2 * DD];
__device__ float g_contrib[NN * 4];
__device__ float g_dinv[NN];
__device__ int   g_off[NN + 1];
__device__ int   g_col[EE];

// ---------------- merged graph prep (one block) ----------------
__global__ __launch_bounds__(1024) void prep_kernel(const int* __restrict__ ei) {
    __shared__ int scnt[NN];
    __shared__ int csum[1024];
    const int tid = threadIdx.x;
    scnt[tid] = 0; scnt[tid + 1024] = 0;
    __syncthreads();
    for (int e = tid; e < EE; e += 1024) atomicAdd(&scnt[ei[EE + e]], 1);
    __syncthreads();
    int a = scnt[2 * tid], b = scnt[2 * tid + 1];
    csum[tid] = a + b;
    __syncthreads();
    for (int ofs = 1; ofs < 1024; ofs <<= 1) {
        int v = (tid >= ofs) ? csum[tid - ofs] : 0;
        __syncthreads();
        csum[tid] += v;
        __syncthreads();
    }
    int pre = (tid == 0) ? 0 : csum[tid - 1];
    g_off[2 * tid]     = pre;
    g_off[2 * tid + 1] = pre + a;
    g_dinv[2 * tid]     = rsqrtf((float)(a + 1));
    g_dinv[2 * tid + 1] = rsqrtf((float)(b + 1));
    if (tid == 1023) g_off[NN] = pre + a + b;
    __syncthreads();
    scnt[2 * tid] = pre; scnt[2 * tid + 1] = pre + a;   // reuse as cursors
    __syncthreads();
    for (int e = tid; e < EE; e += 1024) {
        int src = ei[e], dst = ei[EE + e];
        int p = atomicAdd(&scnt[dst], 1);
        g_col[p] = src;
    }
}

// ---------------- fused CNN + pos-MLP (one block per node, f32x2) ----------------
// smem float offsets
#define SXP_O   0        // 1048
#define H1_O    1048     // 8*1028
#define U1_O    9280     // 8*1024
#define H2_O    0        // 16*253 (reuse)
#define U2_O    4048     // 16*248 (reuse)
#define W1E_O   17472    // 96 float2 = 192
#define W1O_O   17664    // 192
#define W1X_O   17856    // 16
#define W2K_O   17872    // 512 float4 = 2048
#define W3K_O   19920    // 1024 float4 = 4096
#define S1_O    24016
#define B1_O    24024
#define S2_O    24032
#define B2_O    24048
#define S3_O    24064
#define B3_O    24096
#define PE_O    24128
#define HID_O   24160
#define CONV_SMEM_FLOATS 24192
#define CONV_SMEM_BYTES (CONV_SMEM_FLOATS * 4)

__global__ __launch_bounds__(256, 2) void conv_kernel(
    const float* __restrict__ x,   const float* __restrict__ pos,
    const float* __restrict__ c1w, const float* __restrict__ c1b,
    const float* __restrict__ g1,  const float* __restrict__ b1,
    const float* __restrict__ c2w, const float* __restrict__ c2b,
    const float* __restrict__ g2,  const float* __restrict__ b2,
    const float* __restrict__ c3w, const float* __restrict__ c3b,
    const float* __restrict__ g3,  const float* __restrict__ b3,
    const float* __restrict__ pw1, const float* __restrict__ pb1,
    const float* __restrict__ pw2, const float* __restrict__ pb2,
    float* __restrict__ out)
{
    extern __shared__ float sm[];
    const int n = blockIdx.x;
    const int tid = threadIdx.x;
    const float rs = rsqrtf(1.0f + 1e-5f);

    // ---- weight staging (paired layouts) ----
    for (int i = tid; i < 96; i += 256) {          // conv1 even-pairs
        int c = i / 12, m = i % 12;
        sm[W1E_O + 2 * i]     = c1w[c * 25 + 2 * m];
        sm[W1E_O + 2 * i + 1] = c1w[c * 25 + 2 * m + 1];
    }
    for (int i = tid; i < 96; i += 256) {          // conv1 odd-pairs
        int c = i / 12, m = i % 12;
        sm[W1O_O + 2 * i]     = c1w[c * 25 + 2 * m + 1];
        sm[W1O_O + 2 * i + 1] = c1w[c * 25 + 2 * m + 2];
    }
    if (tid < 8)  sm[W1X_O + tid] = c1w[tid * 25];           // w[0]
    else if (tid < 16) sm[W1X_O + tid] = c1w[(tid - 8) * 25 + 24]; // w[24]
    for (int i = tid; i < 512; i += 256) {         // conv2: (ci*8+m)*8+q -> float4
        int ci = i >> 6, m = (i >> 3) & 7, q = i & 7;
        int base = q * 120 + ci * 15 + 2 * m;
        float4 v;
        v.x = c2w[base];
        v.y = (2 * m + 1 < 15) ? c2w[base + 1] : 0.f;
        v.z = c2w[base + 960];
        v.w = (2 * m + 1 < 15) ? c2w[base + 961] : 0.f;
        *(float4*)&sm[W2K_O + 4 * i] = v;
    }
    for (int i = tid; i < 1024; i += 256) {        // conv3: (ci*4+m)*16+q -> float4
        int ci = i >> 6, m = (i >> 4) & 3, q = i & 15;
        int base = q * 112 + ci * 7 + 2 * m;
        float4 v;
        v.x = c3w[base];
        v.y = (2 * m + 1 < 7) ? c3w[base + 1] : 0.f;
        v.z = c3w[base + 1792];
        v.w = (2 * m + 1 < 7) ? c3w[base + 1793] : 0.f;
        *(float4*)&sm[W3K_O + 4 * i] = v;
    }
    if (tid < 8) {
        float s = g1[tid] * rs; sm[S1_O + tid] = s; sm[B1_O + tid] = c1b[tid] * s + b1[tid];
    } else if (tid >= 32 && tid < 48) {
        int c = tid - 32; float s = g2[c] * rs; sm[S2_O + c] = s; sm[B2_O + c] = c2b[c] * s + b2[c];
    } else if (tid >= 64 && tid < 96) {
        int c = tid - 64; float s = g3[c] * rs; sm[S3_O + c] = s; sm[B3_O + c] = c3b[c] * s + b3[c];
    }
    if (tid >= 128 && tid < 160) {
        int c = tid - 128;
        float p0 = pos[n * 3 + 0], p1 = pos[n * 3 + 1], p2 = pos[n * 3 + 2];
        float h = p0 * pw1[c] + p1 * pw1[32 + c] + p2 * pw1[64 + c] + pb1[c];
        sm[HID_O + c] = fmaxf(h, 0.f);
    }
    for (int i = tid; i < 1024; i += 256) sm[SXP_O + 12 + i] = x[(size_t)n * 1024 + i];
    if (tid < 12) { sm[SXP_O + tid] = 0.f; sm[SXP_O + 1036 + tid] = 0.f; }
    __syncthreads();

    if (tid < 32) {                                // pos-MLP layer 2
        float s = pb2[tid];
#pragma unroll
        for (int j = 0; j < 32; j++) s += sm[HID_O + j] * pw2[j * 32 + tid];
        sm[PE_O + tid] = s;
    }

    // ---- conv1: thread handles 4 consecutive t for all 8 channels ----
    {
        const int t0 = tid * 4;
        union UU { float4 q[7]; u64b p[14]; float f[28]; } uu;
#pragma unroll
        for (int i = 0; i < 7; i++) uu.q[i] = *(const float4*)&sm[SXP_O + t0 + 4 * i];
        const u64b* w1e = (const u64b*)&sm[W1E_O];
        const u64b* w1o = (const u64b*)&sm[W1O_O];
#pragma unroll
        for (int c = 0; c < 8; c++) {
            u64b a0 = 0, a1 = 0, a2 = 0, a3 = 0;
#pragma unroll
            for (int m = 0; m < 12; m++) {
                u64b we = w1e[c * 12 + m];
                fma2(a0, we, uu.p[m]);
                fma2(a2, we, uu.p[m + 1]);
                u64b wo = w1o[c * 12 + m];
                fma2(a1, wo, uu.p[m + 1]);
                fma2(a3, wo, uu.p[m + 2]);
            }
            float w0 = sm[W1X_O + c], w24 = sm[W1X_O + 8 + c];
            float v0 = hsum2(a0) + w24 * uu.f[24];
            float v1 = hsum2(a1) + w0  * uu.f[1];
            float v2 = hsum2(a2) + w24 * uu.f[26];
            float v3 = hsum2(a3) + w0  * uu.f[3];
            float s = sm[S1_O + c], B = sm[B1_O + c];
            float4 o;
            o.x = fmaxf(v0 * s + B, 0.f);
            o.y = fmaxf(v1 * s + B, 0.f);
            o.z = fmaxf(v2 * s + B, 0.f);
            o.w = fmaxf(v3 * s + B, 0.f);
            *(float4*)&sm[H1_O + c * 1028 + t0] = o;
        }
    }
    __syncthreads();

    // ---- u1 = 4-window mean of h1 ----
    for (int j = tid; j < 8 * 1020; j += 256) {
        int c = j / 1020, jj = j % 1020;
        const float* hr = &sm[H1_O + c * 1028 + jj];
        sm[U1_O + c * 1024 + jj] = 0.25f * (hr[0] + hr[1] + hr[2] + hr[3]);
    }
    __syncthreads();

    // ---- conv2 (8->16, K=15 padded to 16) fused pool4, channels (q, q+8) ----
    {
        const int q = tid & 7, tpq = tid >> 3;
        u64b accL[8], accH[8];
#pragma unroll
        for (int it = 0; it < 8; it++) { accL[it] = 0; accH[it] = 0; }
#pragma unroll
        for (int ci = 0; ci < 8; ci++) {
            union WU { float4 v; u64b p[2]; } wv[8];
#pragma unroll
            for (int m = 0; m < 8; m++)
                wv[m].v = *(const float4*)&sm[W2K_O + 4 * ((ci * 8 + m) * 8 + q)];
#pragma unroll
            for (int it = 0; it < 8; it++) {
                int tp = tpq + 32 * it;
                if (tp < 252) {
                    union UB { float4 v[4]; u64b p[8]; } ub;
                    const float4* up = (const float4*)&sm[U1_O + ci * 1024 + 4 * tp];
#pragma unroll
                    for (int i = 0; i < 4; i++) ub.v[i] = up[i];
#pragma unroll
                    for (int m = 0; m < 8; m++) {
                        fma2(accL[it], wv[m].p[0], ub.p[m]);
                        fma2(accH[it], wv[m].p[1], ub.p[m]);
                    }
                }
            }
        }
        float sL = sm[S2_O + q], BL = sm[B2_O + q];
        float sH = sm[S2_O + q + 8], BH = sm[B2_O + q + 8];
#pragma unroll
        for (int it = 0; it < 8; it++) {
            int tp = tpq + 32 * it;
            if (tp < 252) {
                sm[H2_O + q * 253 + tp]       = fmaxf(hsum2(accL[it]) * sL + BL, 0.f);
                sm[H2_O + (q + 8) * 253 + tp] = fmaxf(hsum2(accH[it]) * sH + BH, 0.f);
            }
        }
    }
    __syncthreads();

    // ---- u2 = 4-window mean of h2 ----
    for (int j = tid; j < 16 * 248; j += 256) {
        int c = j / 248, jj = j % 248;
        const float* hr = &sm[H2_O + c * 253 + jj];
        sm[U2_O + c * 248 + jj] = 0.25f * (hr[0] + hr[1] + hr[2] + hr[3]);
    }
    __syncthreads();

    // ---- conv3 (16->32, K=7 padded to 8) fused pool4 + pe, channels (q, q+16) ----
    {
        const int q = tid & 15, tpq = tid >> 4;
        u64b accL[4], accH[4];
#pragma unroll
        for (int it = 0; it < 4; it++) { accL[it] = 0; accH[it] = 0; }
#pragma unroll
        for (int ci = 0; ci < 16; ci++) {
            union WU { float4 v; u64b p[2]; } wv[4];
#pragma unroll
            for (int m = 0; m < 4; m++)
                wv[m].v = *(const float4*)&sm[W3K_O + 4 * ((ci * 4 + m) * 16 + q)];
#pragma unroll
            for (int it = 0; it < 4; it++) {
                int tp = tpq + 16 * it;
                if (tp < 61) {
                    union UB { float4 v[2]; u64b p[4]; } ub;
                    const float4* up = (const float4*)&sm[U2_O + ci * 248 + 4 * tp];
                    ub.v[0] = up[0]; ub.v[1] = up[1];
#pragma unroll
                    for (int m = 0; m < 4; m++) {
                        fma2(accL[it], wv[m].p[0], ub.p[m]);
                        fma2(accH[it], wv[m].p[1], ub.p[m]);
                    }
                }
            }
        }
        float sL = sm[S3_O + q], BL = sm[B3_O + q], peL = sm[PE_O + q];
        float sH = sm[S3_O + q + 16], BH = sm[B3_O + q + 16], peH = sm[PE_O + q + 16];
#pragma unroll
        for (int it = 0; it < 4; it++) {
            int tp = tpq + 16 * it;
            if (tp < 61) {
                size_t base = ((size_t)n * 61 + tp) * 32;
                out[base + q]      = fmaxf(hsum2(accL[it]) * sL + BL, 0.f) + peL;
                out[base + q + 16] = fmaxf(hsum2(accH[it]) * sH + BH, 0.f) + peH;
            }
        }
    }
}

// ---------------- GCN aggregation (float4 gather) ----------------
template <int C>
__global__ __launch_bounds__(256) void agg_kernel(const float* __restrict__ h,
                                                  float* __restrict__ s)
{
    constexpr int V4 = TP2 * C / 4;
    constexpr int VPT = (V4 + 255) / 256;
    const int n = blockIdx.x, tid = threadIdx.x;
    const float dvn = g_dinv[n];
    const float4* hn = (const float4*)(h + (size_t)n * (TP2 * C));
    float4 acc[VPT];
#pragma unroll
    for (int v = 0; v < VPT; v++) {
        int i = tid + v * 256;
        if (i < V4) {
            float4 t = hn[i];
            acc[v] = make_float4(t.x * dvn, t.y * dvn, t.z * dvn, t.w * dvn);
        } else acc[v] = make_float4(0.f, 0.f, 0.f, 0.f);
    }
    const int jb = g_off[n], je = g_off[n + 1];
    for (int j = jb; j < je; j++) {
        const int src = g_col[j];
        const float dv = g_dinv[src];
        const float4* hs = (const float4*)(h + (size_t)src * (TP2 * C));
#pragma unroll
        for (int v = 0; v < VPT; v++) {
            int i = tid + v * 256;
            if (i < V4) {
                float4 t = hs[i];
                acc[v].x += t.x * dv; acc[v].y += t.y * dv;
                acc[v].z += t.z * dv; acc[v].w += t.w * dv;
            }
        }
    }
    float4* sn = (float4*)(s + (size_t)n * (TP2 * C));
#pragma unroll
    for (int v = 0; v < VPT; v++) {
        int i = tid + v * 256;
        if (i < V4) sn[i] = acc[v];
    }
}

// ---------------- tf32 tensor-core GEMM ----------------
template <int K>
__global__ __launch_bounds__(256) void gemm_tc_kernel(
    const float* __restrict__ A, const float* __restrict__ W,
    const float* __restrict__ bias, float* __restrict__ out)
{
    constexpr int LDA = K + 4;
    constexpr int LDW = 132;
    constexpr int LDC = 132;
    extern __shared__ float sg[];
    float* ws = sg;
    float* as = sg + K * LDW;
    float* cs = as;
    __shared__ float bs[128];

    const int tid = threadIdx.x;
    const int wid = tid >> 5;
    const int wr = wid & 3;
    const int wc = wid >> 2;
    const int row0 = blockIdx.x * 128;

    if (tid < 128) bs[tid] = bias[tid];
    for (int i = tid; i < K * 32; i += 256) {
        int k = i >> 5, c4 = i & 31;
        float4 v = *(const float4*)&W[k * 128 + c4 * 4];
        *(float4*)&ws[k * LDW + c4 * 4] = v;
    }
    for (int i = tid; i < 128 * (K / 4); i += 256) {
        int r = i / (K / 4), c4 = i % (K / 4);
        float4 v = *(const float4*)&A[(size_t)(row0 + r) * K + c4 * 4];
        *(float4*)&as[r * LDA + c4 * 4] = v;
    }
    __syncthreads();

    wmma::fragment<wmma::accumulator, 16, 16, 8, float> cf[2][4];
#pragma unroll
    for (int i = 0; i < 2; i++)
#pragma unroll
        for (int j = 0; j < 4; j++) wmma::fill_fragment(cf[i][j], 0.f);

#pragma unroll
    for (int k0 = 0; k0 < K; k0 += 8) {
        wmma::fragment<wmma::matrix_a, 16, 16, 8, wmma::precision::tf32, wmma::row_major> af[2];
#pragma unroll
        for (int i = 0; i < 2; i++) {
            wmma::load_matrix_sync(af[i], as + (wr * 32 + i * 16) * LDA + k0, LDA);
#pragma unroll
            for (int t = 0; t < af[i].num_elements; t++)
                af[i].x[t] = wmma::__float_to_tf32(af[i].x[t]);
        }
        wmma::fragment<wmma::matrix_b, 16, 16, 8, wmma::precision::tf32, wmma::row_major> bf[4];
#pragma unroll
        for (int j = 0; j < 4; j++) {
            wmma::load_matrix_sync(bf[j], ws + k0 * LDW + wc * 64 + j * 16, LDW);
#pragma unroll
            for (int t = 0; t < bf[j].num_elements; t++)
                bf[j].x[t] = wmma::__float_to_tf32(bf[j].x[t]);
        }
#pragma unroll
        for (int i = 0; i < 2; i++)
#pragma unroll
            for (int j = 0; j < 4; j++)
                wmma::mma_sync(cf[i][j], af[i], bf[j], cf[i][j]);
    }
    __syncthreads();
#pragma unroll
    for (int i = 0; i < 2; i++)
#pragma unroll
        for (int j = 0; j < 4; j++)
            wmma::store_matrix_sync(cs + (wr * 32 + i * 16) * LDC + wc * 64 + j * 16,
                                    cf[i][j], LDC, wmma::mem_row_major);
    __syncthreads();

    for (int idx = tid; idx < 128 * 128; idx += 256) {
        int r = idx >> 7, c = idx & 127;
        int row = row0 + r;
        float dv = g_dinv[row / 61];
        out[(size_t)row * 128 + c] = fmaxf(cs[r * LDC + c] * dv + bs[c], 0.f);
    }
}

// ---------------- per-node dense contribution ----------------
__global__ __launch_bounds__(256) void contrib_kernel(
    const float* __restrict__ h, const float* __restrict__ dw)
{
    const int n = blockIdx.x, tid = threadIdx.x;
    const float* hn = h + (size_t)n * (TP2 * DD);
    float a0 = 0.f, a1 = 0.f, a2 = 0.f, a3 = 0.f;
    for (int e = tid; e < TP2 * DD; e += 256) {
        int t = e >> 7, d = e & 127;
        float v = hn[e];
        const float4 w = *(const float4*)&dw[(size_t)(d * 61 + t) * 4];
        a0 += v * w.x; a1 += v * w.y; a2 += v * w.z; a3 += v * w.w;
    }
    __shared__ float r0[256], r1[256], r2[256], r3[256];
    r0[tid] = a0; r1[tid] = a1; r2[tid] = a2; r3[tid] = a3;
    __syncthreads();
    for (int s = 128; s > 0; s >>= 1) {
        if (tid < s) {
            r0[tid] += r0[tid + s]; r1[tid] += r1[tid + s];
            r2[tid] += r2[tid + s]; r3[tid] += r3[tid + s];
        }
        __syncthreads();
    }
    if (tid == 0) {
        g_contrib[n * 4 + 0] = r0[0];
        g_contrib[n * 4 + 1] = r1[0];
        g_contrib[n * 4 + 2] = r2[0];
        g_contrib[n * 4 + 3] = r3[0];
    }
}

// ---------------- batch pooling + bias + log_softmax ----------------
__global__ __launch_bounds__(256) void final_kernel(
    const int* __restrict__ batch, const float* __restrict__ db,
    float* __restrict__ out)
{
    const int b = blockIdx.x, tid = threadIdx.x;
    float a0 = 0.f, a1 = 0.f, a2 = 0.f, a3 = 0.f;
    int c = 0;
    for (int n = tid; n < NN; n += 256) {
        if (batch[n] == b) {
            const float4 v = *(const float4*)&g_contrib[n * 4];
            a0 += v.x; a1 += v.y; a2 += v.z; a3 += v.w;
            c++;
        }
    }
    __shared__ float r0[256], r1[256], r2[256], r3[256];
    __shared__ int rc[256];
    r0[tid] = a0; r1[tid] = a1; r2[tid] = a2; r3[tid] = a3; rc[tid] = c;
    __syncthreads();
    for (int s = 128; s > 0; s >>= 1) {
        if (tid < s) {
            r0[tid] += r0[tid + s]; r1[tid] += r1[tid + s];
            r2[tid] += r2[tid + s]; r3[tid] += r3[tid + s];
            rc[tid] += rc[tid + s];
        }
        __syncthreads();
    }
    if (tid == 0) {
        float cc = fmaxf((float)rc[0], 1.f);
        float l0 = r0[0] / cc + db[0];
        float l1 = r1[0] / cc + db[1];
        float l2 = r2[0] / cc + db[2];
        float l3 = r3[0] / cc + db[3];
        float m = fmaxf(fmaxf(l0, l1), fmaxf(l2, l3));
        float sum = expf(l0 - m) + expf(l1 - m) + expf(l2 - m) + expf(l3 - m);
        float ls = logf(sum);
        out[b * 4 + 0] = l0 - m - ls;
        out[b * 4 + 1] = l1 - m - ls;
        out[b * 4 + 2] = l2 - m - ls;
        out[b * 4 + 3] = l3 - m - ls;
    }
}

// ---------------- launch ----------------
extern "C" void kernel_launch(void* const* d_in, const int* in_sizes, int n_in,
                              void* d_out, int out_size)
{
    const float* x   = (const float*)d_in[0];
    const float* pos = (const float*)d_in[1];
    const float* c1w = (const float*)d_in[2];
    const float* c1b = (const float*)d_in[3];
    const float* bg1 = (const float*)d_in[4];
    const float* bb1 = (const float*)d_in[5];
    const float* c2w = (const float*)d_in[6];
    const float* c2b = (const float*)d_in[7];
    const float* bg2 = (const float*)d_in[8];
    const float* bb2 = (const float*)d_in[9];
    const float* c3w = (const float*)d_in[10];
    const float* c3b = (const float*)d_in[11];
    const float* bg3 = (const float*)d_in[12];
    const float* bb3 = (const float*)d_in[13];
    const float* pw1 = (const float*)d_in[14];
    const float* pb1 = (const float*)d_in[15];
    const float* pw2 = (const float*)d_in[16];
    const float* pb2 = (const float*)d_in[17];
    const float* gw1 = (const float*)d_in[18];
    const float* gb1 = (const float*)d_in[19];
    const float* gw2 = (const float*)d_in[20];
    const float* gb2 = (const float*)d_in[21];
    const float* dw  = (const float*)d_in[22];
    const float* db  = (const float*)d_in[23];
    const int*   ei  = (const int*)d_in[24];
    const int*   bat = (const int*)d_in[25];
    float* out = (float*)d_out;

    const int gemm32_smem  = (32 * 132 + 128 * 132) * 4;
    const int gemm128_smem = (128 * 132 + 128 * 132) * 4;

    cudaFuncSetAttribute(conv_kernel, cudaFuncAttributeMaxDynamicSharedMemorySize, CONV_SMEM_BYTES);
    cudaFuncSetAttribute(gemm_tc_kernel<32>,  cudaFuncAttributeMaxDynamicSharedMemorySize, gemm32_smem);
    cudaFuncSetAttribute(gemm_tc_kernel<128>, cudaFuncAttributeMaxDynamicSharedMemorySize, gemm128_smem);

    float *h0, *s0, *h1, *s1, *h2;
    cudaGetSymbolAddress((void**)&h0, g_h0);
    cudaGetSymbolAddress((void**)&s0, g_s0);
    cudaGetSymbolAddress((void**)&h1, g_h1);
    cudaGetSymbolAddress((void**)&s1, g_s1);
    cudaGetSymbolAddress((void**)&h2, g_h2);

    prep_kernel<<<1, 1024>>>(ei);

    conv_kernel<<<NN, 256, CONV_SMEM_BYTES>>>(
        x, pos, c1w, c1b, bg1, bb1, c2w, c2b, bg2, bb2,
        c3w, c3b, bg3, bb3, pw1, pb1, pw2, pb2, h0);

    agg_kernel<32><<<NN, 256>>>(h0, s0);
    gemm_tc_kernel<32><<<(NN * TP2) / 128, 256, gemm32_smem>>>(s0, gw1, gb1, h1);

    agg_kernel<128><<<NN, 256>>>(h1, s1);
    gemm_tc_kernel<128><<<(NN * TP2) / 128, 256, gemm128_smem>>>(s1, gw2, gb2, h2);

    contrib_kernel<<<NN, 256>>>(h2, dw);
    final_kernel<<<BBATCH, 256>>>(bat, db, out);
}

// round 5
// speedup vs baseline: 1.6478x; 1.2593x over previous
#include <cuda_runtime.h>
#include <cuda_bf16.h>
#include <math.h>
#include <mma.h>

using namespace nvcuda;

#define NN     2048
#define EE     16384
#define BBATCH 32
#define TP2    61
#define DD     128
#define C3N    32

typedef unsigned long long u64b;

__device__ __forceinline__ void fma2(u64b& d, u64b a, u64b b) {
    asm("fma.rn.f32x2 %0, %1, %2, %0;" : "+l"(d) : "l"(a), "l"(b));
}
__device__ __forceinline__ float hsum2(u64b v) {
    float lo, hi;
    asm("mov.b64 {%0,%1}, %2;" : "=f"(lo), "=f"(hi) : "l"(v));
    return lo + hi;
}

__device__ __forceinline__ void bf8_to_f8(uint4 u, float* f) {
    const __nv_bfloat162* p = (const __nv_bfloat162*)&u;
#pragma unroll
    for (int j = 0; j < 4; j++) {
        float2 t = __bfloat1622float2(p[j]);
        f[2 * j] = t.x; f[2 * j + 1] = t.y;
    }
}
__device__ __forceinline__ uint4 f8_to_bf8(const float* f) {
    uint4 u;
    __nv_bfloat162* p = (__nv_bfloat162*)&u;
#pragma unroll
    for (int j = 0; j < 4; j++) p[j] = __floats2bfloat162_rn(f[2 * j], f[2 * j + 1]);
    return u;
}

// ---------------- scratch ----------------
__device__ __nv_bfloat16 g_h0[NN * TP2 * C3N];
__device__ __nv_bfloat16 g_s0[NN * TP2 * C3N];
__device__ __nv_bfloat16 g_h1[NN * TP2 * DD];
__device__ __nv_bfloat16 g_s1[NN * TP2 * DD];
__device__ __nv_bfloat16 g_h2[NN * TP2 * DD];
__device__ float g_contrib[NN * 4];
__device__ float g_dinv[NN];
__device__ int   g_off[NN + 1];
__device__ int   g_col[EE];

// ---------------- merged graph prep (one block) ----------------
__global__ __launch_bounds__(1024) void prep_kernel(const int* __restrict__ ei) {
    __shared__ int scnt[NN];
    __shared__ int csum[1024];
    const int tid = threadIdx.x;
    scnt[tid] = 0; scnt[tid + 1024] = 0;
    __syncthreads();
    for (int e = tid; e < EE; e += 1024) atomicAdd(&scnt[ei[EE + e]], 1);
    __syncthreads();
    int a = scnt[2 * tid], b = scnt[2 * tid + 1];
    csum[tid] = a + b;
    __syncthreads();
    for (int ofs = 1; ofs < 1024; ofs <<= 1) {
        int v = (tid >= ofs) ? csum[tid - ofs] : 0;
        __syncthreads();
        csum[tid] += v;
        __syncthreads();
    }
    int pre = (tid == 0) ? 0 : csum[tid - 1];
    g_off[2 * tid]     = pre;
    g_off[2 * tid + 1] = pre + a;
    g_dinv[2 * tid]     = rsqrtf((float)(a + 1));
    g_dinv[2 * tid + 1] = rsqrtf((float)(b + 1));
    if (tid == 1023) g_off[NN] = pre + a + b;
    __syncthreads();
    scnt[2 * tid] = pre; scnt[2 * tid + 1] = pre + a;
    __syncthreads();
    for (int e = tid; e < EE; e += 1024) {
        int src = ei[e], dst = ei[EE + e];
        int p = atomicAdd(&scnt[dst], 1);
        g_col[p] = src;
    }
}

// ---------------- fused CNN + pos-MLP (one block per node, f32x2) ----------------
#define SXP_O   0
#define H1_O    1048
#define U1_O    9280
#define H2_O    0
#define U2_O    4048
#define W1E_O   17472
#define W1O_O   17664
#define W1X_O   17856
#define W2K_O   17872
#define W3K_O   19920
#define S1_O    24016
#define B1_O    24024
#define S2_O    24032
#define B2_O    24048
#define S3_O    24064
#define B3_O    24096
#define PE_O    24128
#define HID_O   24160
#define CONV_SMEM_FLOATS 24192
#define CONV_SMEM_BYTES (CONV_SMEM_FLOATS * 4)

__global__ __launch_bounds__(256, 2) void conv_kernel(
    const float* __restrict__ x,   const float* __restrict__ pos,
    const float* __restrict__ c1w, const float* __restrict__ c1b,
    const float* __restrict__ g1,  const float* __restrict__ b1,
    const float* __restrict__ c2w, const float* __restrict__ c2b,
    const float* __restrict__ g2,  const float* __restrict__ b2,
    const float* __restrict__ c3w, const float* __restrict__ c3b,
    const float* __restrict__ g3,  const float* __restrict__ b3,
    const float* __restrict__ pw1, const float* __restrict__ pb1,
    const float* __restrict__ pw2, const float* __restrict__ pb2,
    __nv_bfloat16* __restrict__ out)
{
    extern __shared__ float sm[];
    const int n = blockIdx.x;
    const int tid = threadIdx.x;
    const float rs = rsqrtf(1.0f + 1e-5f);

    for (int i = tid; i < 96; i += 256) {
        int c = i / 12, m = i % 12;
        sm[W1E_O + 2 * i]     = c1w[c * 25 + 2 * m];
        sm[W1E_O + 2 * i + 1] = c1w[c * 25 + 2 * m + 1];
    }
    for (int i = tid; i < 96; i += 256) {
        int c = i / 12, m = i % 12;
        sm[W1O_O + 2 * i]     = c1w[c * 25 + 2 * m + 1];
        sm[W1O_O + 2 * i + 1] = c1w[c * 25 + 2 * m + 2];
    }
    if (tid < 8)  sm[W1X_O + tid] = c1w[tid * 25];
    else if (tid < 16) sm[W1X_O + tid] = c1w[(tid - 8) * 25 + 24];
    for (int i = tid; i < 512; i += 256) {
        int ci = i >> 6, m = (i >> 3) & 7, q = i & 7;
        int base = q * 120 + ci * 15 + 2 * m;
        float4 v;
        v.x = c2w[base];
        v.y = (2 * m + 1 < 15) ? c2w[base + 1] : 0.f;
        v.z = c2w[base + 960];
        v.w = (2 * m + 1 < 15) ? c2w[base + 961] : 0.f;
        *(float4*)&sm[W2K_O + 4 * i] = v;
    }
    for (int i = tid; i < 1024; i += 256) {
        int ci = i >> 6, m = (i >> 4) & 3, q = i & 15;
        int base = q * 112 + ci * 7 + 2 * m;
        float4 v;
        v.x = c3w[base];
        v.y = (2 * m + 1 < 7) ? c3w[base + 1] : 0.f;
        v.z = c3w[base + 1792];
        v.w = (2 * m + 1 < 7) ? c3w[base + 1793] : 0.f;
        *(float4*)&sm[W3K_O + 4 * i] = v;
    }
    if (tid < 8) {
        float s = g1[tid] * rs; sm[S1_O + tid] = s; sm[B1_O + tid] = c1b[tid] * s + b1[tid];
    } else if (tid >= 32 && tid < 48) {
        int c = tid - 32; float s = g2[c] * rs; sm[S2_O + c] = s; sm[B2_O + c] = c2b[c] * s + b2[c];
    } else if (tid >= 64 && tid < 96) {
        int c = tid - 64; float s = g3[c] * rs; sm[S3_O + c] = s; sm[B3_O + c] = c3b[c] * s + b3[c];
    }
    if (tid >= 128 && tid < 160) {
        int c = tid - 128;
        float p0 = pos[n * 3 + 0], p1 = pos[n * 3 + 1], p2 = pos[n * 3 + 2];
        float h = p0 * pw1[c] + p1 * pw1[32 + c] + p2 * pw1[64 + c] + pb1[c];
        sm[HID_O + c] = fmaxf(h, 0.f);
    }
    for (int i = tid; i < 1024; i += 256) sm[SXP_O + 12 + i] = x[(size_t)n * 1024 + i];
    if (tid < 12) { sm[SXP_O + tid] = 0.f; sm[SXP_O + 1036 + tid] = 0.f; }
    __syncthreads();

    if (tid < 32) {
        float s = pb2[tid];
#pragma unroll
        for (int j = 0; j < 32; j++) s += sm[HID_O + j] * pw2[j * 32 + tid];
        sm[PE_O + tid] = s;
    }

    // conv1
    {
        const int t0 = tid * 4;
        union UU { float4 q[7]; u64b p[14]; float f[28]; } uu;
#pragma unroll
        for (int i = 0; i < 7; i++) uu.q[i] = *(const float4*)&sm[SXP_O + t0 + 4 * i];
        const u64b* w1e = (const u64b*)&sm[W1E_O];
        const u64b* w1o = (const u64b*)&sm[W1O_O];
#pragma unroll
        for (int c = 0; c < 8; c++) {
            u64b a0 = 0, a1 = 0, a2 = 0, a3 = 0;
#pragma unroll
            for (int m = 0; m < 12; m++) {
                u64b we = w1e[c * 12 + m];
                fma2(a0, we, uu.p[m]);
                fma2(a2, we, uu.p[m + 1]);
                u64b wo = w1o[c * 12 + m];
                fma2(a1, wo, uu.p[m + 1]);
                fma2(a3, wo, uu.p[m + 2]);
            }
            float w0 = sm[W1X_O + c], w24 = sm[W1X_O + 8 + c];
            float v0 = hsum2(a0) + w24 * uu.f[24];
            float v1 = hsum2(a1) + w0  * uu.f[1];
            float v2 = hsum2(a2) + w24 * uu.f[26];
            float v3 = hsum2(a3) + w0  * uu.f[3];
            float s = sm[S1_O + c], B = sm[B1_O + c];
            float4 o;
            o.x = fmaxf(v0 * s + B, 0.f);
            o.y = fmaxf(v1 * s + B, 0.f);
            o.z = fmaxf(v2 * s + B, 0.f);
            o.w = fmaxf(v3 * s + B, 0.f);
            *(float4*)&sm[H1_O + c * 1028 + t0] = o;
        }
    }
    __syncthreads();

    for (int j = tid; j < 8 * 1020; j += 256) {
        int c = j / 1020, jj = j % 1020;
        const float* hr = &sm[H1_O + c * 1028 + jj];
        sm[U1_O + c * 1024 + jj] = 0.25f * (hr[0] + hr[1] + hr[2] + hr[3]);
    }
    __syncthreads();

    // conv2
    {
        const int q = tid & 7, tpq = tid >> 3;
        u64b accL[8], accH[8];
#pragma unroll
        for (int it = 0; it < 8; it++) { accL[it] = 0; accH[it] = 0; }
#pragma unroll
        for (int ci = 0; ci < 8; ci++) {
            union WU { float4 v; u64b p[2]; } wv[8];
#pragma unroll
            for (int m = 0; m < 8; m++)
                wv[m].v = *(const float4*)&sm[W2K_O + 4 * ((ci * 8 + m) * 8 + q)];
#pragma unroll
            for (int it = 0; it < 8; it++) {
                int tp = tpq + 32 * it;
                if (tp < 252) {
                    union UB { float4 v[4]; u64b p[8]; } ub;
                    const float4* up = (const float4*)&sm[U1_O + ci * 1024 + 4 * tp];
#pragma unroll
                    for (int i = 0; i < 4; i++) ub.v[i] = up[i];
#pragma unroll
                    for (int m = 0; m < 8; m++) {
                        fma2(accL[it], wv[m].p[0], ub.p[m]);
                        fma2(accH[it], wv[m].p[1], ub.p[m]);
                    }
                }
            }
        }
        float sL = sm[S2_O + q], BL = sm[B2_O + q];
        float sH = sm[S2_O + q + 8], BH = sm[B2_O + q + 8];
#pragma unroll
        for (int it = 0; it < 8; it++) {
            int tp = tpq + 32 * it;
            if (tp < 252) {
                sm[H2_O + q * 253 + tp]       = fmaxf(hsum2(accL[it]) * sL + BL, 0.f);
                sm[H2_O + (q + 8) * 253 + tp] = fmaxf(hsum2(accH[it]) * sH + BH, 0.f);
            }
        }
    }
    __syncthreads();

    for (int j = tid; j < 16 * 248; j += 256) {
        int c = j / 248, jj = j % 248;
        const float* hr = &sm[H2_O + c * 253 + jj];
        sm[U2_O + c * 248 + jj] = 0.25f * (hr[0] + hr[1] + hr[2] + hr[3]);
    }
    __syncthreads();

    // conv3 + pe, write bf16 (n,t,c)
    {
        const int q = tid & 15, tpq = tid >> 4;
        u64b accL[4], accH[4];
#pragma unroll
        for (int it = 0; it < 4; it++) { accL[it] = 0; accH[it] = 0; }
#pragma unroll
        for (int ci = 0; ci < 16; ci++) {
            union WU { float4 v; u64b p[2]; } wv[4];
#pragma unroll
            for (int m = 0; m < 4; m++)
                wv[m].v = *(const float4*)&sm[W3K_O + 4 * ((ci * 4 + m) * 16 + q)];
#pragma unroll
            for (int it = 0; it < 4; it++) {
                int tp = tpq + 16 * it;
                if (tp < 61) {
                    union UB { float4 v[2]; u64b p[4]; } ub;
                    const float4* up = (const float4*)&sm[U2_O + ci * 248 + 4 * tp];
                    ub.v[0] = up[0]; ub.v[1] = up[1];
#pragma unroll
                    for (int m = 0; m < 4; m++) {
                        fma2(accL[it], wv[m].p[0], ub.p[m]);
                        fma2(accH[it], wv[m].p[1], ub.p[m]);
                    }
                }
            }
        }
        float sL = sm[S3_O + q], BL = sm[B3_O + q], peL = sm[PE_O + q];
        float sH = sm[S3_O + q + 16], BH = sm[B3_O + q + 16], peH = sm[PE_O + q + 16];
#pragma unroll
        for (int it = 0; it < 4; it++) {
            int tp = tpq + 16 * it;
            if (tp < 61) {
                size_t base = ((size_t)n * 61 + tp) * 32;
                out[base + q]      = __float2bfloat16(fmaxf(hsum2(accL[it]) * sL + BL, 0.f) + peL);
                out[base + q + 16] = __float2bfloat16(fmaxf(hsum2(accH[it]) * sH + BH, 0.f) + peH);
            }
        }
    }
}

// ---------------- GCN aggregation: bf16 in/out, fp32 accumulate ----------------
template <int C>
__global__ __launch_bounds__(256) void agg_kernel(const __nv_bfloat16* __restrict__ h,
                                                  __nv_bfloat16* __restrict__ s)
{
    constexpr int V8 = TP2 * C / 8;          // 244 (C=32) / 976 (C=128)
    constexpr int VPT = (V8 + 255) / 256;    // 1 / 4
    const int n = blockIdx.x, tid = threadIdx.x;
    const float dvn = g_dinv[n];
    const uint4* hn = (const uint4*)(h + (size_t)n * (TP2 * C));
    float acc[VPT][8];
#pragma unroll
    for (int v = 0; v < VPT; v++) {
        int i = tid + v * 256;
        if (i < V8) {
            float f[8];
            bf8_to_f8(hn[i], f);
#pragma unroll
            for (int j = 0; j < 8; j++) acc[v][j] = f[j] * dvn;
        } else {
#pragma unroll
            for (int j = 0; j < 8; j++) acc[v][j] = 0.f;
        }
    }
    const int jb = g_off[n], je = g_off[n + 1];
    for (int e = jb; e < je; e++) {
        const int src = g_col[e];
        const float dv = g_dinv[src];
        const uint4* hs = (const uint4*)(h + (size_t)src * (TP2 * C));
#pragma unroll
        for (int v = 0; v < VPT; v++) {
            int i = tid + v * 256;
            if (i < V8) {
                float f[8];
                bf8_to_f8(hs[i], f);
#pragma unroll
                for (int j = 0; j < 8; j++) acc[v][j] += f[j] * dv;
            }
        }
    }
    uint4* sn = (uint4*)(s + (size_t)n * (TP2 * C));
#pragma unroll
    for (int v = 0; v < VPT; v++) {
        int i = tid + v * 256;
        if (i < V8) sn[i] = f8_to_bf8(acc[v]);
    }
}

// ---------------- bf16 tensor-core GEMM ----------------
// out[M,128](bf16) = relu((A[M,K](bf16) @ W[K,128](f32->bf16)) * dinv[row/61] + bias)
template <int K>
__global__ __launch_bounds__(256) void gemm_bf16_kernel(
    const __nv_bfloat16* __restrict__ A, const float* __restrict__ W,
    const float* __restrict__ bias, __nv_bfloat16* __restrict__ out)
{
    constexpr int LDA = K + 8;
    constexpr int LDW = 136;
    constexpr int LDC = 132;
    extern __shared__ char sgc[];
    __nv_bfloat16* ws = (__nv_bfloat16*)sgc;           // K * LDW
    __nv_bfloat16* as = ws + K * LDW;                   // 128 * LDA
    float* cs = (float*)sgc;                            // reuse for C (128*LDC f32)
    __shared__ float bs[128];

    const int tid = threadIdx.x;
    const int wid = tid >> 5;
    const int wr = wid & 3;
    const int wc = wid >> 2;
    const int row0 = blockIdx.x * 128;

    if (tid < 128) bs[tid] = bias[tid];
    for (int i = tid; i < K * 32; i += 256) {
        int k = i >> 5, c4 = i & 31;
        float4 v = *(const float4*)&W[k * 128 + c4 * 4];
        __nv_bfloat16* p = &ws[k * LDW + c4 * 4];
        p[0] = __float2bfloat16(v.x); p[1] = __float2bfloat16(v.y);
        p[2] = __float2bfloat16(v.z); p[3] = __float2bfloat16(v.w);
    }
    for (int i = tid; i < 128 * (K / 8); i += 256) {
        int r = i / (K / 8), c8 = i % (K / 8);
        *(uint4*)&as[r * LDA + c8 * 8] =
            *(const uint4*)&A[(size_t)(row0 + r) * K + c8 * 8];
    }
    __syncthreads();

    wmma::fragment<wmma::accumulator, 16, 16, 16, float> cf[2][4];
#pragma unroll
    for (int i = 0; i < 2; i++)
#pragma unroll
        for (int j = 0; j < 4; j++) wmma::fill_fragment(cf[i][j], 0.f);

#pragma unroll
    for (int k0 = 0; k0 < K; k0 += 16) {
        wmma::fragment<wmma::matrix_a, 16, 16, 16, __nv_bfloat16, wmma::row_major> af[2];
#pragma unroll
        for (int i = 0; i < 2; i++)
            wmma::load_matrix_sync(af[i], as + (wr * 32 + i * 16) * LDA + k0, LDA);
        wmma::fragment<wmma::matrix_b, 16, 16, 16, __nv_bfloat16, wmma::row_major> bf[4];
#pragma unroll
        for (int j = 0; j < 4; j++)
            wmma::load_matrix_sync(bf[j], ws + k0 * LDW + wc * 64 + j * 16, LDW);
#pragma unroll
        for (int i = 0; i < 2; i++)
#pragma unroll
            for (int j = 0; j < 4; j++)
                wmma::mma_sync(cf[i][j], af[i], bf[j], cf[i][j]);
    }
    __syncthreads();   // input tiles dead; reuse as C
#pragma unroll
    for (int i = 0; i < 2; i++)
#pragma unroll
        for (int j = 0; j < 4; j++)
            wmma::store_matrix_sync(cs + (wr * 32 + i * 16) * LDC + wc * 64 + j * 16,
                                    cf[i][j], LDC, wmma::mem_row_major);
    __syncthreads();

    // epilogue: *dinv + bias, relu, bf16x2 stores
    for (int idx = tid; idx < 128 * 64; idx += 256) {
        int r = idx >> 6, c2 = idx & 63;
        int row = row0 + r;
        float dv = g_dinv[row / 61];
        float v0 = fmaxf(cs[r * LDC + 2 * c2]     * dv + bs[2 * c2], 0.f);
        float v1 = fmaxf(cs[r * LDC + 2 * c2 + 1] * dv + bs[2 * c2 + 1], 0.f);
        ((__nv_bfloat162*)out)[(size_t)row * 64 + c2] = __floats2bfloat162_rn(v0, v1);
    }
}

// ---------------- per-node dense contribution (bf16 h2) ----------------
__global__ __launch_bounds__(256) void contrib_kernel(
    const __nv_bfloat16* __restrict__ h, const float* __restrict__ dw)
{
    const int n = blockIdx.x, tid = threadIdx.x;
    const uint4* hn = (const uint4*)(h + (size_t)n * (TP2 * DD));
    float a0 = 0.f, a1 = 0.f, a2 = 0.f, a3 = 0.f;
    for (int i = tid; i < 976; i += 256) {      // 976 uint4 = 7808 bf16
        int t = i >> 4, d0 = (i & 15) * 8;
        float f[8];
        bf8_to_f8(hn[i], f);
#pragma unroll
        for (int j = 0; j < 8; j++) {
            const float4 w = *(const float4*)&dw[(size_t)((d0 + j) * 61 + t) * 4];
            a0 += f[j] * w.x; a1 += f[j] * w.y; a2 += f[j] * w.z; a3 += f[j] * w.w;
        }
    }
    __shared__ float r0[256], r1[256], r2[256], r3[256];
    r0[tid] = a0; r1[tid] = a1; r2[tid] = a2; r3[tid] = a3;
    __syncthreads();
    for (int s = 128; s > 0; s >>= 1) {
        if (tid < s) {
            r0[tid] += r0[tid + s]; r1[tid] += r1[tid + s];
            r2[tid] += r2[tid + s]; r3[tid] += r3[tid + s];
        }
        __syncthreads();
    }
    if (tid == 0) {
        g_contrib[n * 4 + 0] = r0[0];
        g_contrib[n * 4 + 1] = r1[0];
        g_contrib[n * 4 + 2] = r2[0];
        g_contrib[n * 4 + 3] = r3[0];
    }
}

// ---------------- batch pooling + bias + log_softmax ----------------
__global__ __launch_bounds__(256) void final_kernel(
    const int* __restrict__ batch, const float* __restrict__ db,
    float* __restrict__ out)
{
    const int b = blockIdx.x, tid = threadIdx.x;
    float a0 = 0.f, a1 = 0.f, a2 = 0.f, a3 = 0.f;
    int c = 0;
    for (int n = tid; n < NN; n += 256) {
        if (batch[n] == b) {
            const float4 v = *(const float4*)&g_contrib[n * 4];
            a0 += v.x; a1 += v.y; a2 += v.z; a3 += v.w;
            c++;
        }
    }
    __shared__ float r0[256], r1[256], r2[256], r3[256];
    __shared__ int rc[256];
    r0[tid] = a0; r1[tid] = a1; r2[tid] = a2; r3[tid] = a3; rc[tid] = c;
    __syncthreads();
    for (int s = 128; s > 0; s >>= 1) {
        if (tid < s) {
            r0[tid] += r0[tid + s]; r1[tid] += r1[tid + s];
            r2[tid] += r2[tid + s]; r3[tid] += r3[tid + s];
            rc[tid] += rc[tid + s];
        }
        __syncthreads();
    }
    if (tid == 0) {
        float cc = fmaxf((float)rc[0], 1.f);
        float l0 = r0[0] / cc + db[0];
        float l1 = r1[0] / cc + db[1];
        float l2 = r2[0] / cc + db[2];
        float l3 = r3[0] / cc + db[3];
        float m = fmaxf(fmaxf(l0, l1), fmaxf(l2, l3));
        float sum = expf(l0 - m) + expf(l1 - m) + expf(l2 - m) + expf(l3 - m);
        float ls = logf(sum);
        out[b * 4 + 0] = l0 - m - ls;
        out[b * 4 + 1] = l1 - m - ls;
        out[b * 4 + 2] = l2 - m - ls;
        out[b * 4 + 3] = l3 - m - ls;
    }
}

// ---------------- launch ----------------
extern "C" void kernel_launch(void* const* d_in, const int* in_sizes, int n_in,
                              void* d_out, int out_size)
{
    const float* x   = (const float*)d_in[0];
    const float* pos = (const float*)d_in[1];
    const float* c1w = (const float*)d_in[2];
    const float* c1b = (const float*)d_in[3];
    const float* bg1 = (const float*)d_in[4];
    const float* bb1 = (const float*)d_in[5];
    const float* c2w = (const float*)d_in[6];
    const float* c2b = (const float*)d_in[7];
    const float* bg2 = (const float*)d_in[8];
    const float* bb2 = (const float*)d_in[9];
    const float* c3w = (const float*)d_in[10];
    const float* c3b = (const float*)d_in[11];
    const float* bg3 = (const float*)d_in[12];
    const float* bb3 = (const float*)d_in[13];
    const float* pw1 = (const float*)d_in[14];
    const float* pb1 = (const float*)d_in[15];
    const float* pw2 = (const float*)d_in[16];
    const float* pb2 = (const float*)d_in[17];
    const float* gw1 = (const float*)d_in[18];
    const float* gb1 = (const float*)d_in[19];
    const float* gw2 = (const float*)d_in[20];
    const float* gb2 = (const float*)d_in[21];
    const float* dw  = (const float*)d_in[22];
    const float* db  = (const float*)d_in[23];
    const int*   ei  = (const int*)d_in[24];
    const int*   bat = (const int*)d_in[25];
    float* out = (float*)d_out;

    const int gemm32_smem  = 128 * 132 * 4;                       // 67584 (C reuse dominates)
    const int gemm128_smem = (128 * 136 + 128 * 136) * 2;         // 69632

    cudaFuncSetAttribute(conv_kernel, cudaFuncAttributeMaxDynamicSharedMemorySize, CONV_SMEM_BYTES);
    cudaFuncSetAttribute(gemm_bf16_kernel<32>,  cudaFuncAttributeMaxDynamicSharedMemorySize, gemm32_smem);
    cudaFuncSetAttribute(gemm_bf16_kernel<128>, cudaFuncAttributeMaxDynamicSharedMemorySize, gemm128_smem);

    __nv_bfloat16 *h0, *s0, *h1, *s1, *h2;
    cudaGetSymbolAddress((void**)&h0, g_h0);
    cudaGetSymbolAddress((void**)&s0, g_s0);
    cudaGetSymbolAddress((void**)&h1, g_h1);
    cudaGetSymbolAddress((void**)&s1, g_s1);
    cudaGetSymbolAddress((void**)&h2, g_h2);

    prep_kernel<<<1, 1024>>>(ei);

    conv_kernel<<<NN, 256, CONV_SMEM_BYTES>>>(
        x, pos, c1w, c1b, bg1, bb1, c2w, c2b, bg2, bb2,
        c3w, c3b, bg3, bb3, pw1, pb1, pw2, pb2, h0);

    agg_kernel<32><<<NN, 256>>>(h0, s0);
    gemm_bf16_kernel<32><<<(NN * TP2) / 128, 256, gemm32_smem>>>(s0, gw1, gb1, h1);

    agg_kernel<128><<<NN, 256>>>(h1, s1);
    gemm_bf16_kernel<128><<<(NN * TP2) / 128, 256, gemm128_smem>>>(s1, gw2, gb2, h2);

    contrib_kernel<<<NN, 256>>>(h2, dw);
    final_kernel<<<BBATCH, 256>>>(bat, db, out);
}

// round 6
// speedup vs baseline: 2.1141x; 1.2829x over previous
#include <cuda_runtime.h>
#include <cuda_bf16.h>
#include <math.h>
#include <mma.h>

using namespace nvcuda;

#define NN     2048
#define EE     16384
#define BBATCH 32
#define TP2    61
#define DD     128
#define C3N    32

typedef unsigned long long u64b;

__device__ __forceinline__ void fma2(u64b& d, u64b a, u64b b) {
    asm("fma.rn.f32x2 %0, %1, %2, %0;" : "+l"(d) : "l"(a), "l"(b));
}
__device__ __forceinline__ float hsum2(u64b v) {
    float lo, hi;
    asm("mov.b64 {%0,%1}, %2;" : "=f"(lo), "=f"(hi) : "l"(v));
    return lo + hi;
}

__device__ __forceinline__ void bf8_to_f8(uint4 u, float* f) {
    const __nv_bfloat162* p = (const __nv_bfloat162*)&u;
#pragma unroll
    for (int j = 0; j < 4; j++) {
        float2 t = __bfloat1622float2(p[j]);
        f[2 * j] = t.x; f[2 * j + 1] = t.y;
    }
}
__device__ __forceinline__ uint4 f8_to_bf8(const float* f) {
    uint4 u;
    __nv_bfloat162* p = (__nv_bfloat162*)&u;
#pragma unroll
    for (int j = 0; j < 4; j++) p[j] = __floats2bfloat162_rn(f[2 * j], f[2 * j + 1]);
    return u;
}

// ---------------- scratch ----------------
__device__ __nv_bfloat16 g_h0[NN * TP2 * C3N];
__device__ __nv_bfloat16 g_h1[NN * TP2 * DD];
__device__ float g_contrib[NN * 4];
__device__ float g_dinv[NN];
__device__ int   g_off[NN + 1];
__device__ int   g_col[EE];

// ---------------- merged graph prep (one block) ----------------
__global__ __launch_bounds__(1024) void prep_kernel(const int* __restrict__ ei) {
    __shared__ int scnt[NN];
    __shared__ int csum[1024];
    const int tid = threadIdx.x;
    scnt[tid] = 0; scnt[tid + 1024] = 0;
    __syncthreads();
    for (int e = tid; e < EE; e += 1024) atomicAdd(&scnt[ei[EE + e]], 1);
    __syncthreads();
    int a = scnt[2 * tid], b = scnt[2 * tid + 1];
    csum[tid] = a + b;
    __syncthreads();
    for (int ofs = 1; ofs < 1024; ofs <<= 1) {
        int v = (tid >= ofs) ? csum[tid - ofs] : 0;
        __syncthreads();
        csum[tid] += v;
        __syncthreads();
    }
    int pre = (tid == 0) ? 0 : csum[tid - 1];
    g_off[2 * tid]     = pre;
    g_off[2 * tid + 1] = pre + a;
    g_dinv[2 * tid]     = rsqrtf((float)(a + 1));
    g_dinv[2 * tid + 1] = rsqrtf((float)(b + 1));
    if (tid == 1023) g_off[NN] = pre + a + b;
    __syncthreads();
    scnt[2 * tid] = pre; scnt[2 * tid + 1] = pre + a;
    __syncthreads();
    for (int e = tid; e < EE; e += 1024) {
        int src = ei[e], dst = ei[EE + e];
        int p = atomicAdd(&scnt[dst], 1);
        g_col[p] = src;
    }
}

// ---------------- fused CNN + pos-MLP (one block per node, f32x2) ----------------
#define SXP_O   0
#define H1_O    1048
#define U1_O    9280
#define H2_O    0
#define U2_O    4048
#define W1E_O   17472
#define W1O_O   17664
#define W1X_O   17856
#define W2K_O   17872
#define W3K_O   19920
#define S1_O    24016
#define B1_O    24024
#define S2_O    24032
#define B2_O    24048
#define S3_O    24064
#define B3_O    24096
#define PE_O    24128
#define HID_O   24160
#define CONV_SMEM_FLOATS 24192
#define CONV_SMEM_BYTES (CONV_SMEM_FLOATS * 4)

__global__ __launch_bounds__(256, 2) void conv_kernel(
    const float* __restrict__ x,   const float* __restrict__ pos,
    const float* __restrict__ c1w, const float* __restrict__ c1b,
    const float* __restrict__ g1,  const float* __restrict__ b1,
    const float* __restrict__ c2w, const float* __restrict__ c2b,
    const float* __restrict__ g2,  const float* __restrict__ b2,
    const float* __restrict__ c3w, const float* __restrict__ c3b,
    const float* __restrict__ g3,  const float* __restrict__ b3,
    const float* __restrict__ pw1, const float* __restrict__ pb1,
    const float* __restrict__ pw2, const float* __restrict__ pb2,
    __nv_bfloat16* __restrict__ out)
{
    extern __shared__ float sm[];
    const int n = blockIdx.x;
    const int tid = threadIdx.x;
    const float rs = rsqrtf(1.0f + 1e-5f);

    for (int i = tid; i < 96; i += 256) {
        int c = i / 12, m = i % 12;
        sm[W1E_O + 2 * i]     = c1w[c * 25 + 2 * m];
        sm[W1E_O + 2 * i + 1] = c1w[c * 25 + 2 * m + 1];
    }
    for (int i = tid; i < 96; i += 256) {
        int c = i / 12, m = i % 12;
        sm[W1O_O + 2 * i]     = c1w[c * 25 + 2 * m + 1];
        sm[W1O_O + 2 * i + 1] = c1w[c * 25 + 2 * m + 2];
    }
    if (tid < 8)  sm[W1X_O + tid] = c1w[tid * 25];
    else if (tid < 16) sm[W1X_O + tid] = c1w[(tid - 8) * 25 + 24];
    for (int i = tid; i < 512; i += 256) {
        int ci = i >> 6, m = (i >> 3) & 7, q = i & 7;
        int base = q * 120 + ci * 15 + 2 * m;
        float4 v;
        v.x = c2w[base];
        v.y = (2 * m + 1 < 15) ? c2w[base + 1] : 0.f;
        v.z = c2w[base + 960];
        v.w = (2 * m + 1 < 15) ? c2w[base + 961] : 0.f;
        *(float4*)&sm[W2K_O + 4 * i] = v;
    }
    for (int i = tid; i < 1024; i += 256) {
        int ci = i >> 6, m = (i >> 4) & 3, q = i & 15;
        int base = q * 112 + ci * 7 + 2 * m;
        float4 v;
        v.x = c3w[base];
        v.y = (2 * m + 1 < 7) ? c3w[base + 1] : 0.f;
        v.z = c3w[base + 1792];
        v.w = (2 * m + 1 < 7) ? c3w[base + 1793] : 0.f;
        *(float4*)&sm[W3K_O + 4 * i] = v;
    }
    if (tid < 8) {
        float s = g1[tid] * rs; sm[S1_O + tid] = s; sm[B1_O + tid] = c1b[tid] * s + b1[tid];
    } else if (tid >= 32 && tid < 48) {
        int c = tid - 32; float s = g2[c] * rs; sm[S2_O + c] = s; sm[B2_O + c] = c2b[c] * s + b2[c];
    } else if (tid >= 64 && tid < 96) {
        int c = tid - 64; float s = g3[c] * rs; sm[S3_O + c] = s; sm[B3_O + c] = c3b[c] * s + b3[c];
    }
    if (tid >= 128 && tid < 160) {
        int c = tid - 128;
        float p0 = pos[n * 3 + 0], p1 = pos[n * 3 + 1], p2 = pos[n * 3 + 2];
        float h = p0 * pw1[c] + p1 * pw1[32 + c] + p2 * pw1[64 + c] + pb1[c];
        sm[HID_O + c] = fmaxf(h, 0.f);
    }
    for (int i = tid; i < 1024; i += 256) sm[SXP_O + 12 + i] = x[(size_t)n * 1024 + i];
    if (tid < 12) { sm[SXP_O + tid] = 0.f; sm[SXP_O + 1036 + tid] = 0.f; }
    __syncthreads();

    if (tid < 32) {
        float s = pb2[tid];
#pragma unroll
        for (int j = 0; j < 32; j++) s += sm[HID_O + j] * pw2[j * 32 + tid];
        sm[PE_O + tid] = s;
    }

    // conv1
    {
        const int t0 = tid * 4;
        union UU { float4 q[7]; u64b p[14]; float f[28]; } uu;
#pragma unroll
        for (int i = 0; i < 7; i++) uu.q[i] = *(const float4*)&sm[SXP_O + t0 + 4 * i];
        const u64b* w1e = (const u64b*)&sm[W1E_O];
        const u64b* w1o = (const u64b*)&sm[W1O_O];
#pragma unroll
        for (int c = 0; c < 8; c++) {
            u64b a0 = 0, a1 = 0, a2 = 0, a3 = 0;
#pragma unroll
            for (int m = 0; m < 12; m++) {
                u64b we = w1e[c * 12 + m];
                fma2(a0, we, uu.p[m]);
                fma2(a2, we, uu.p[m + 1]);
                u64b wo = w1o[c * 12 + m];
                fma2(a1, wo, uu.p[m + 1]);
                fma2(a3, wo, uu.p[m + 2]);
            }
            float w0 = sm[W1X_O + c], w24 = sm[W1X_O + 8 + c];
            float v0 = hsum2(a0) + w24 * uu.f[24];
            float v1 = hsum2(a1) + w0  * uu.f[1];
            float v2 = hsum2(a2) + w24 * uu.f[26];
            float v3 = hsum2(a3) + w0  * uu.f[3];
            float s = sm[S1_O + c], B = sm[B1_O + c];
            float4 o;
            o.x = fmaxf(v0 * s + B, 0.f);
            o.y = fmaxf(v1 * s + B, 0.f);
            o.z = fmaxf(v2 * s + B, 0.f);
            o.w = fmaxf(v3 * s + B, 0.f);
            *(float4*)&sm[H1_O + c * 1028 + t0] = o;
        }
    }
    __syncthreads();

    for (int j = tid; j < 8 * 1020; j += 256) {
        int c = j / 1020, jj = j % 1020;
        const float* hr = &sm[H1_O + c * 1028 + jj];
        sm[U1_O + c * 1024 + jj] = 0.25f * (hr[0] + hr[1] + hr[2] + hr[3]);
    }
    __syncthreads();

    // conv2
    {
        const int q = tid & 7, tpq = tid >> 3;
        u64b accL[8], accH[8];
#pragma unroll
        for (int it = 0; it < 8; it++) { accL[it] = 0; accH[it] = 0; }
#pragma unroll
        for (int ci = 0; ci < 8; ci++) {
            union WU { float4 v; u64b p[2]; } wv[8];
#pragma unroll
            for (int m = 0; m < 8; m++)
                wv[m].v = *(const float4*)&sm[W2K_O + 4 * ((ci * 8 + m) * 8 + q)];
#pragma unroll
            for (int it = 0; it < 8; it++) {
                int tp = tpq + 32 * it;
                if (tp < 252) {
                    union UB { float4 v[4]; u64b p[8]; } ub;
                    const float4* up = (const float4*)&sm[U1_O + ci * 1024 + 4 * tp];
#pragma unroll
                    for (int i = 0; i < 4; i++) ub.v[i] = up[i];
#pragma unroll
                    for (int m = 0; m < 8; m++) {
                        fma2(accL[it], wv[m].p[0], ub.p[m]);
                        fma2(accH[it], wv[m].p[1], ub.p[m]);
                    }
                }
            }
        }
        float sL = sm[S2_O + q], BL = sm[B2_O + q];
        float sH = sm[S2_O + q + 8], BH = sm[B2_O + q + 8];
#pragma unroll
        for (int it = 0; it < 8; it++) {
            int tp = tpq + 32 * it;
            if (tp < 252) {
                sm[H2_O + q * 253 + tp]       = fmaxf(hsum2(accL[it]) * sL + BL, 0.f);
                sm[H2_O + (q + 8) * 253 + tp] = fmaxf(hsum2(accH[it]) * sH + BH, 0.f);
            }
        }
    }
    __syncthreads();

    for (int j = tid; j < 16 * 248; j += 256) {
        int c = j / 248, jj = j % 248;
        const float* hr = &sm[H2_O + c * 253 + jj];
        sm[U2_O + c * 248 + jj] = 0.25f * (hr[0] + hr[1] + hr[2] + hr[3]);
    }
    __syncthreads();

    // conv3 + pe, write bf16 (n,t,c)
    {
        const int q = tid & 15, tpq = tid >> 4;
        u64b accL[4], accH[4];
#pragma unroll
        for (int it = 0; it < 4; it++) { accL[it] = 0; accH[it] = 0; }
#pragma unroll
        for (int ci = 0; ci < 16; ci++) {
            union WU { float4 v; u64b p[2]; } wv[4];
#pragma unroll
            for (int m = 0; m < 4; m++)
                wv[m].v = *(const float4*)&sm[W3K_O + 4 * ((ci * 4 + m) * 16 + q)];
#pragma unroll
            for (int it = 0; it < 4; it++) {
                int tp = tpq + 16 * it;
                if (tp < 61) {
                    union UB { float4 v[2]; u64b p[4]; } ub;
                    const float4* up = (const float4*)&sm[U2_O + ci * 248 + 4 * tp];
                    ub.v[0] = up[0]; ub.v[1] = up[1];
#pragma unroll
                    for (int m = 0; m < 4; m++) {
                        fma2(accL[it], wv[m].p[0], ub.p[m]);
                        fma2(accH[it], wv[m].p[1], ub.p[m]);
                    }
                }
            }
        }
        float sL = sm[S3_O + q], BL = sm[B3_O + q], peL = sm[PE_O + q];
        float sH = sm[S3_O + q + 16], BH = sm[B3_O + q + 16], peH = sm[PE_O + q + 16];
#pragma unroll
        for (int it = 0; it < 4; it++) {
            int tp = tpq + 16 * it;
            if (tp < 61) {
                size_t base = ((size_t)n * 61 + tp) * 32;
                out[base + q]      = __float2bfloat16(fmaxf(hsum2(accL[it]) * sL + BL, 0.f) + peL);
                out[base + q + 16] = __float2bfloat16(fmaxf(hsum2(accH[it]) * sH + BH, 0.f) + peH);
            }
        }
    }
}

// ---------------- fused GCN layer: gather-aggregate + bf16 wmma GEMM ----------------
// One block = 2 nodes = 122 rows (padded to 128).
// DO_CONTRIB=false: write relu((s@W)*dinv+b) to out (bf16).
// DO_CONTRIB=true : compute per-node dense contribs in-block, write g_contrib only.
template <int K, bool DO_CONTRIB>
__global__ __launch_bounds__(256) void gcn_fused_kernel(
    const __nv_bfloat16* __restrict__ h, const float* __restrict__ W,
    const float* __restrict__ bias, __nv_bfloat16* __restrict__ out,
    const float* __restrict__ dw)
{
    constexpr int LDA = K + 8;
    constexpr int LDW = 136;
    constexpr int LDC = 132;
    constexpr int V8 = TP2 * K / 8;          // 244 (K=32) / 976 (K=128)
    constexpr int VPT = (V8 + 255) / 256;    // 1 / 4
    extern __shared__ char sgc[];
    __nv_bfloat16* ws = (__nv_bfloat16*)sgc;   // K * LDW
    __nv_bfloat16* as = ws + K * LDW;           // 128 * LDA
    float* cs = (float*)sgc;                    // reuse for C tile (128 * LDC f32)
    __shared__ float bs[128];
    __shared__ float red[8][4];

    const int tid = threadIdx.x;
    const int bid = blockIdx.x;

    if (tid < 128) bs[tid] = bias[tid];
    for (int i = tid; i < K * 32; i += 256) {
        int k = i >> 5, c4 = i & 31;
        float4 v = *(const float4*)&W[k * 128 + c4 * 4];
        __nv_bfloat16* p = &ws[k * LDW + c4 * 4];
        p[0] = __float2bfloat16(v.x); p[1] = __float2bfloat16(v.y);
        p[2] = __float2bfloat16(v.z); p[3] = __float2bfloat16(v.w);
    }
    // zero pad rows 122..127 of A
    for (int i = tid; i < 6 * (K / 8); i += 256) {
        int r = 122 + i / (K / 8), c8 = i % (K / 8);
        *(uint4*)&as[r * LDA + c8 * 8] = make_uint4(0, 0, 0, 0);
    }

    // gather-aggregate both nodes into A tile (fp32 accumulate, bf16 store)
#pragma unroll
    for (int nh = 0; nh < 2; nh++) {
        const int n = 2 * bid + nh;
        const float dvn = g_dinv[n];
        const uint4* hn = (const uint4*)(h + (size_t)n * (TP2 * K));
        float acc[VPT][8];
#pragma unroll
        for (int v = 0; v < VPT; v++) {
            int i = tid + v * 256;
            if (i < V8) {
                float f[8]; bf8_to_f8(hn[i], f);
#pragma unroll
                for (int j = 0; j < 8; j++) acc[v][j] = f[j] * dvn;
            }
        }
        const int jb = g_off[n], je = g_off[n + 1];
        for (int e = jb; e < je; e++) {
            const int src = g_col[e];
            const float dv = g_dinv[src];
            const uint4* hs = (const uint4*)(h + (size_t)src * (TP2 * K));
#pragma unroll
            for (int v = 0; v < VPT; v++) {
                int i = tid + v * 256;
                if (i < V8) {
                    float f[8]; bf8_to_f8(hs[i], f);
#pragma unroll
                    for (int j = 0; j < 8; j++) acc[v][j] += f[j] * dv;
                }
            }
        }
#pragma unroll
        for (int v = 0; v < VPT; v++) {
            int i = tid + v * 256;
            if (i < V8) {
                int r = nh * TP2 + i / (K / 8), c8 = i % (K / 8);
                *(uint4*)&as[r * LDA + c8 * 8] = f8_to_bf8(acc[v]);
            }
        }
    }
    __syncthreads();

    // wmma: 8 warps (4 row x 2 col), warp tile 32x64
    const int wid = tid >> 5;
    const int wr = wid & 3;
    const int wc = wid >> 2;
    wmma::fragment<wmma::accumulator, 16, 16, 16, float> cf[2][4];
#pragma unroll
    for (int i = 0; i < 2; i++)
#pragma unroll
        for (int j = 0; j < 4; j++) wmma::fill_fragment(cf[i][j], 0.f);

#pragma unroll
    for (int k0 = 0; k0 < K; k0 += 16) {
        wmma::fragment<wmma::matrix_a, 16, 16, 16, __nv_bfloat16, wmma::row_major> af[2];
#pragma unroll
        for (int i = 0; i < 2; i++)
            wmma::load_matrix_sync(af[i], as + (wr * 32 + i * 16) * LDA + k0, LDA);
        wmma::fragment<wmma::matrix_b, 16, 16, 16, __nv_bfloat16, wmma::row_major> bf[4];
#pragma unroll
        for (int j = 0; j < 4; j++)
            wmma::load_matrix_sync(bf[j], ws + k0 * LDW + wc * 64 + j * 16, LDW);
#pragma unroll
        for (int i = 0; i < 2; i++)
#pragma unroll
            for (int j = 0; j < 4; j++)
                wmma::mma_sync(cf[i][j], af[i], bf[j], cf[i][j]);
    }
    __syncthreads();   // input tiles dead; reuse as C
#pragma unroll
    for (int i = 0; i < 2; i++)
#pragma unroll
        for (int j = 0; j < 4; j++)
            wmma::store_matrix_sync(cs + (wr * 32 + i * 16) * LDC + wc * 64 + j * 16,
                                    cf[i][j], LDC, wmma::mem_row_major);
    __syncthreads();

    if (!DO_CONTRIB) {
        // epilogue: *dinv + bias, relu, bf16x2 stores to out
        for (int idx = tid; idx < 128 * 64; idx += 256) {
            int r = idx >> 6, c2 = idx & 63;
            if (r < 122) {
                int nh = (r >= TP2) ? 1 : 0;
                int n = 2 * bid + nh;
                int t = r - TP2 * nh;
                float dv = g_dinv[n];
                float v0 = fmaxf(cs[r * LDC + 2 * c2]     * dv + bs[2 * c2], 0.f);
                float v1 = fmaxf(cs[r * LDC + 2 * c2 + 1] * dv + bs[2 * c2 + 1], 0.f);
                ((__nv_bfloat162*)out)[(size_t)(n * TP2 + t) * 64 + c2] =
                    __floats2bfloat162_rn(v0, v1);
            }
        }
    } else {
        // fused contrib: per-node dot with dense weights, deterministic reduce
        const int half = tid >> 7, d = tid & 127;
        const int n = 2 * bid + half;
        const float dv = g_dinv[n];
        const float bsv = bs[d];
        float a0 = 0.f, a1 = 0.f, a2 = 0.f, a3 = 0.f;
#pragma unroll 4
        for (int t = 0; t < TP2; t++) {
            float v = fmaxf(cs[(half * TP2 + t) * LDC + d] * dv + bsv, 0.f);
            const float4 w = *(const float4*)&dw[(size_t)(d * TP2 + t) * 4];
            a0 += v * w.x; a1 += v * w.y; a2 += v * w.z; a3 += v * w.w;
        }
#pragma unroll
        for (int o = 16; o > 0; o >>= 1) {
            a0 += __shfl_down_sync(0xffffffff, a0, o);
            a1 += __shfl_down_sync(0xffffffff, a1, o);
            a2 += __shfl_down_sync(0xffffffff, a2, o);
            a3 += __shfl_down_sync(0xffffffff, a3, o);
        }
        if ((tid & 31) == 0) {
            red[wid][0] = a0; red[wid][1] = a1; red[wid][2] = a2; red[wid][3] = a3;
        }
        __syncthreads();
        if (tid < 8) {
            int hh = tid >> 2, j = tid & 3;
            float s = red[hh * 4 + 0][j] + red[hh * 4 + 1][j]
                    + red[hh * 4 + 2][j] + red[hh * 4 + 3][j];
            g_contrib[(2 * bid + hh) * 4 + j] = s;
        }
    }
}

// ---------------- batch pooling + bias + log_softmax ----------------
__global__ __launch_bounds__(256) void final_kernel(
    const int* __restrict__ batch, const float* __restrict__ db,
    float* __restrict__ out)
{
    const int b = blockIdx.x, tid = threadIdx.x;
    float a0 = 0.f, a1 = 0.f, a2 = 0.f, a3 = 0.f;
    int c = 0;
    for (int n = tid; n < NN; n += 256) {
        if (batch[n] == b) {
            const float4 v = *(const float4*)&g_contrib[n * 4];
            a0 += v.x; a1 += v.y; a2 += v.z; a3 += v.w;
            c++;
        }
    }
    __shared__ float r0[256], r1[256], r2[256], r3[256];
    __shared__ int rc[256];
    r0[tid] = a0; r1[tid] = a1; r2[tid] = a2; r3[tid] = a3; rc[tid] = c;
    __syncthreads();
    for (int s = 128; s > 0; s >>= 1) {
        if (tid < s) {
            r0[tid] += r0[tid + s]; r1[tid] += r1[tid + s];
            r2[tid] += r2[tid + s]; r3[tid] += r3[tid + s];
            rc[tid] += rc[tid + s];
        }
        __syncthreads();
    }
    if (tid == 0) {
        float cc = fmaxf((float)rc[0], 1.f);
        float l0 = r0[0] / cc + db[0];
        float l1 = r1[0] / cc + db[1];
        float l2 = r2[0] / cc + db[2];
        float l3 = r3[0] / cc + db[3];
        float m = fmaxf(fmaxf(l0, l1), fmaxf(l2, l3));
        float sum = expf(l0 - m) + expf(l1 - m) + expf(l2 - m) + expf(l3 - m);
        float ls = logf(sum);
        out[b * 4 + 0] = l0 - m - ls;
        out[b * 4 + 1] = l1 - m - ls;
        out[b * 4 + 2] = l2 - m - ls;
        out[b * 4 + 3] = l3 - m - ls;
    }
}

// ---------------- launch ----------------
extern "C" void kernel_launch(void* const* d_in, const int* in_sizes, int n_in,
                              void* d_out, int out_size)
{
    const float* x   = (const float*)d_in[0];
    const float* pos = (const float*)d_in[1];
    const float* c1w = (const float*)d_in[2];
    const float* c1b = (const float*)d_in[3];
    const float* bg1 = (const float*)d_in[4];
    const float* bb1 = (const float*)d_in[5];
    const float* c2w = (const float*)d_in[6];
    const float* c2b = (const float*)d_in[7];
    const float* bg2 = (const float*)d_in[8];
    const float* bb2 = (const float*)d_in[9];
    const float* c3w = (const float*)d_in[10];
    const float* c3b = (const float*)d_in[11];
    const float* bg3 = (const float*)d_in[12];
    const float* bb3 = (const float*)d_in[13];
    const float* pw1 = (const float*)d_in[14];
    const float* pb1 = (const float*)d_in[15];
    const float* pw2 = (const float*)d_in[16];
    const float* pb2 = (const float*)d_in[17];
    const float* gw1 = (const float*)d_in[18];
    const float* gb1 = (const float*)d_in[19];
    const float* gw2 = (const float*)d_in[20];
    const float* gb2 = (const float*)d_in[21];
    const float* dw  = (const float*)d_in[22];
    const float* db  = (const float*)d_in[23];
    const int*   ei  = (const int*)d_in[24];
    const int*   bat = (const int*)d_in[25];
    float* out = (float*)d_out;

    const int g1_smem = 128 * 132 * 4;                    // 67584 (C tile dominates)
    const int g2_smem = (128 * 136 + 128 * 136) * 2;      // 69632

    cudaFuncSetAttribute(conv_kernel, cudaFuncAttributeMaxDynamicSharedMemorySize, CONV_SMEM_BYTES);
    cudaFuncSetAttribute(gcn_fused_kernel<32, false>,  cudaFuncAttributeMaxDynamicSharedMemorySize, g1_smem);
    cudaFuncSetAttribute(gcn_fused_kernel<128, true>,  cudaFuncAttributeMaxDynamicSharedMemorySize, g2_smem);

    __nv_bfloat16 *h0, *h1;
    cudaGetSymbolAddress((void**)&h0, g_h0);
    cudaGetSymbolAddress((void**)&h1, g_h1);

    prep_kernel<<<1, 1024>>>(ei);

    conv_kernel<<<NN, 256, CONV_SMEM_BYTES>>>(
        x, pos, c1w, c1b, bg1, bb1, c2w, c2b, bg2, bb2,
        c3w, c3b, bg3, bb3, pw1, pb1, pw2, pb2, h0);

    gcn_fused_kernel<32, false><<<NN / 2, 256, g1_smem>>>(h0, gw1, gb1, h1, nullptr);
    gcn_fused_kernel<128, true><<<NN / 2, 256, g2_smem>>>(h1, gw2, gb2, nullptr, dw);

    final_kernel<<<BBATCH, 256>>>(bat, db, out);
}

// round 7
// speedup vs baseline: 2.1668x; 1.0249x over previous
#include <cuda_runtime.h>
#include <cuda_bf16.h>
#include <math.h>
#include <mma.h>

using namespace nvcuda;

#define NN     2048
#define EE     16384
#define BBATCH 32
#define TP2    61
#define DD     128
#define C3N    32

typedef unsigned long long u64b;

__device__ __forceinline__ void fma2(u64b& d, u64b a, u64b b) {
    asm("fma.rn.f32x2 %0, %1, %2, %0;" : "+l"(d) : "l"(a), "l"(b));
}
__device__ __forceinline__ float hsum2(u64b v) {
    float lo, hi;
    asm("mov.b64 {%0,%1}, %2;" : "=f"(lo), "=f"(hi) : "l"(v));
    return lo + hi;
}
// bf16x2 (packed in u32) -> f32x2 pair (lo elem in low word): f32 = bf16 << 16
__device__ __forceinline__ u64b expand_bf2(unsigned u) {
    unsigned lo = u << 16;
    unsigned hi = u & 0xffff0000u;
    u64b d;
    asm("mov.b64 %0, {%1, %2};" : "=l"(d) : "r"(lo), "r"(hi));
    return d;
}
__device__ __forceinline__ void add2(u64b& d, u64b a) {
    asm("add.rn.f32x2 %0, %0, %1;" : "+l"(d) : "l"(a));
}
__device__ __forceinline__ void acc_u4(u64b* accp, uint4 b) {
    add2(accp[0], expand_bf2(b.x));
    add2(accp[1], expand_bf2(b.y));
    add2(accp[2], expand_bf2(b.z));
    add2(accp[3], expand_bf2(b.w));
}
__device__ __forceinline__ unsigned pair_to_bf2(u64b d) {
    float lo, hi; unsigned r;
    asm("mov.b64 {%0,%1}, %2;" : "=f"(lo), "=f"(hi) : "l"(d));
    asm("cvt.rn.bf16x2.f32 %0, %1, %2;" : "=r"(r) : "f"(hi), "f"(lo));
    return r;
}

// ---------------- scratch ----------------
__device__ __nv_bfloat16 g_h0[NN * TP2 * C3N];
__device__ __nv_bfloat16 g_h1[NN * TP2 * DD];
__device__ float g_contrib[NN * 4];
__device__ float g_dinv[NN];
__device__ int   g_off[NN + 1];
__device__ int   g_col[EE];

// ---------------- merged graph prep (one block) ----------------
__global__ __launch_bounds__(1024) void prep_kernel(const int* __restrict__ ei) {
    __shared__ int scnt[NN];
    __shared__ int csum[1024];
    const int tid = threadIdx.x;
    scnt[tid] = 0; scnt[tid + 1024] = 0;
    __syncthreads();
    for (int e = tid; e < EE; e += 1024) atomicAdd(&scnt[ei[EE + e]], 1);
    __syncthreads();
    int a = scnt[2 * tid], b = scnt[2 * tid + 1];
    csum[tid] = a + b;
    __syncthreads();
    for (int ofs = 1; ofs < 1024; ofs <<= 1) {
        int v = (tid >= ofs) ? csum[tid - ofs] : 0;
        __syncthreads();
        csum[tid] += v;
        __syncthreads();
    }
    int pre = (tid == 0) ? 0 : csum[tid - 1];
    g_off[2 * tid]     = pre;
    g_off[2 * tid + 1] = pre + a;
    g_dinv[2 * tid]     = rsqrtf((float)(a + 1));
    g_dinv[2 * tid + 1] = rsqrtf((float)(b + 1));
    if (tid == 1023) g_off[NN] = pre + a + b;
    __syncthreads();
    scnt[2 * tid] = pre; scnt[2 * tid + 1] = pre + a;
    __syncthreads();
    for (int e = tid; e < EE; e += 1024) {
        int src = ei[e], dst = ei[EE + e];
        int p = atomicAdd(&scnt[dst], 1);
        g_col[p] = src;
    }
}

// ---------------- fused CNN + pos-MLP (one block per node, f32x2) ----------------
#define SXP_O   0
#define H1_O    1048
#define U1_O    9280
#define H2_O    0
#define U2_O    4048
#define W1E_O   17472
#define W1O_O   17664
#define W1X_O   17856
#define W2K_O   17872
#define W3K_O   19920
#define S1_O    24016
#define B1_O    24024
#define S2_O    24032
#define B2_O    24048
#define S3_O    24064
#define B3_O    24096
#define PE_O    24128
#define HID_O   24160
#define CONV_SMEM_FLOATS 24192
#define CONV_SMEM_BYTES (CONV_SMEM_FLOATS * 4)

__global__ __launch_bounds__(256, 2) void conv_kernel(
    const float* __restrict__ x,   const float* __restrict__ pos,
    const float* __restrict__ c1w, const float* __restrict__ c1b,
    const float* __restrict__ g1,  const float* __restrict__ b1,
    const float* __restrict__ c2w, const float* __restrict__ c2b,
    const float* __restrict__ g2,  const float* __restrict__ b2,
    const float* __restrict__ c3w, const float* __restrict__ c3b,
    const float* __restrict__ g3,  const float* __restrict__ b3,
    const float* __restrict__ pw1, const float* __restrict__ pb1,
    const float* __restrict__ pw2, const float* __restrict__ pb2,
    __nv_bfloat16* __restrict__ out)
{
    extern __shared__ float sm[];
    const int n = blockIdx.x;
    const int tid = threadIdx.x;
    const float rs = rsqrtf(1.0f + 1e-5f);
    const float dvn = g_dinv[n];            // folded next-layer source scaling

    for (int i = tid; i < 96; i += 256) {
        int c = i / 12, m = i % 12;
        sm[W1E_O + 2 * i]     = c1w[c * 25 + 2 * m];
        sm[W1E_O + 2 * i + 1] = c1w[c * 25 + 2 * m + 1];
    }
    for (int i = tid; i < 96; i += 256) {
        int c = i / 12, m = i % 12;
        sm[W1O_O + 2 * i]     = c1w[c * 25 + 2 * m + 1];
        sm[W1O_O + 2 * i + 1] = c1w[c * 25 + 2 * m + 2];
    }
    if (tid < 8)  sm[W1X_O + tid] = c1w[tid * 25];
    else if (tid < 16) sm[W1X_O + tid] = c1w[(tid - 8) * 25 + 24];
    for (int i = tid; i < 512; i += 256) {
        int ci = i >> 6, m = (i >> 3) & 7, q = i & 7;
        int base = q * 120 + ci * 15 + 2 * m;
        float4 v;
        v.x = c2w[base];
        v.y = (2 * m + 1 < 15) ? c2w[base + 1] : 0.f;
        v.z = c2w[base + 960];
        v.w = (2 * m + 1 < 15) ? c2w[base + 961] : 0.f;
        *(float4*)&sm[W2K_O + 4 * i] = v;
    }
    for (int i = tid; i < 1024; i += 256) {
        int ci = i >> 6, m = (i >> 4) & 3, q = i & 15;
        int base = q * 112 + ci * 7 + 2 * m;
        float4 v;
        v.x = c3w[base];
        v.y = (2 * m + 1 < 7) ? c3w[base + 1] : 0.f;
        v.z = c3w[base + 1792];
        v.w = (2 * m + 1 < 7) ? c3w[base + 1793] : 0.f;
        *(float4*)&sm[W3K_O + 4 * i] = v;
    }
    if (tid < 8) {
        float s = g1[tid] * rs; sm[S1_O + tid] = s; sm[B1_O + tid] = c1b[tid] * s + b1[tid];
    } else if (tid >= 32 && tid < 48) {
        int c = tid - 32; float s = g2[c] * rs; sm[S2_O + c] = s; sm[B2_O + c] = c2b[c] * s + b2[c];
    } else if (tid >= 64 && tid < 96) {
        int c = tid - 64; float s = g3[c] * rs; sm[S3_O + c] = s; sm[B3_O + c] = c3b[c] * s + b3[c];
    }
    if (tid >= 128 && tid < 160) {
        int c = tid - 128;
        float p0 = pos[n * 3 + 0], p1 = pos[n * 3 + 1], p2 = pos[n * 3 + 2];
        float h = p0 * pw1[c] + p1 * pw1[32 + c] + p2 * pw1[64 + c] + pb1[c];
        sm[HID_O + c] = fmaxf(h, 0.f);
    }
    for (int i = tid; i < 1024; i += 256) sm[SXP_O + 12 + i] = x[(size_t)n * 1024 + i];
    if (tid < 12) { sm[SXP_O + tid] = 0.f; sm[SXP_O + 1036 + tid] = 0.f; }
    __syncthreads();

    if (tid < 32) {
        float s = pb2[tid];
#pragma unroll
        for (int j = 0; j < 32; j++) s += sm[HID_O + j] * pw2[j * 32 + tid];
        sm[PE_O + tid] = s;
    }

    // conv1
    {
        const int t0 = tid * 4;
        union UU { float4 q[7]; u64b p[14]; float f[28]; } uu;
#pragma unroll
        for (int i = 0; i < 7; i++) uu.q[i] = *(const float4*)&sm[SXP_O + t0 + 4 * i];
        const u64b* w1e = (const u64b*)&sm[W1E_O];
        const u64b* w1o = (const u64b*)&sm[W1O_O];
#pragma unroll
        for (int c = 0; c < 8; c++) {
            u64b a0 = 0, a1 = 0, a2 = 0, a3 = 0;
#pragma unroll
            for (int m = 0; m < 12; m++) {
                u64b we = w1e[c * 12 + m];
                fma2(a0, we, uu.p[m]);
                fma2(a2, we, uu.p[m + 1]);
                u64b wo = w1o[c * 12 + m];
                fma2(a1, wo, uu.p[m + 1]);
                fma2(a3, wo, uu.p[m + 2]);
            }
            float w0 = sm[W1X_O + c], w24 = sm[W1X_O + 8 + c];
            float v0 = hsum2(a0) + w24 * uu.f[24];
            float v1 = hsum2(a1) + w0  * uu.f[1];
            float v2 = hsum2(a2) + w24 * uu.f[26];
            float v3 = hsum2(a3) + w0  * uu.f[3];
            float s = sm[S1_O + c], B = sm[B1_O + c];
            float4 o;
            o.x = fmaxf(v0 * s + B, 0.f);
            o.y = fmaxf(v1 * s + B, 0.f);
            o.z = fmaxf(v2 * s + B, 0.f);
            o.w = fmaxf(v3 * s + B, 0.f);
            *(float4*)&sm[H1_O + c * 1028 + t0] = o;
        }
    }
    __syncthreads();

    for (int j = tid; j < 8 * 1020; j += 256) {
        int c = j / 1020, jj = j % 1020;
        const float* hr = &sm[H1_O + c * 1028 + jj];
        sm[U1_O + c * 1024 + jj] = 0.25f * (hr[0] + hr[1] + hr[2] + hr[3]);
    }
    __syncthreads();

    // conv2
    {
        const int q = tid & 7, tpq = tid >> 3;
        u64b accL[8], accH[8];
#pragma unroll
        for (int it = 0; it < 8; it++) { accL[it] = 0; accH[it] = 0; }
#pragma unroll
        for (int ci = 0; ci < 8; ci++) {
            union WU { float4 v; u64b p[2]; } wv[8];
#pragma unroll
            for (int m = 0; m < 8; m++)
                wv[m].v = *(const float4*)&sm[W2K_O + 4 * ((ci * 8 + m) * 8 + q)];
#pragma unroll
            for (int it = 0; it < 8; it++) {
                int tp = tpq + 32 * it;
                if (tp < 252) {
                    union UB { float4 v[4]; u64b p[8]; } ub;
                    const float4* up = (const float4*)&sm[U1_O + ci * 1024 + 4 * tp];
#pragma unroll
                    for (int i = 0; i < 4; i++) ub.v[i] = up[i];
#pragma unroll
                    for (int m = 0; m < 8; m++) {
                        fma2(accL[it], wv[m].p[0], ub.p[m]);
                        fma2(accH[it], wv[m].p[1], ub.p[m]);
                    }
                }
            }
        }
        float sL = sm[S2_O + q], BL = sm[B2_O + q];
        float sH = sm[S2_O + q + 8], BH = sm[B2_O + q + 8];
#pragma unroll
        for (int it = 0; it < 8; it++) {
            int tp = tpq + 32 * it;
            if (tp < 252) {
                sm[H2_O + q * 253 + tp]       = fmaxf(hsum2(accL[it]) * sL + BL, 0.f);
                sm[H2_O + (q + 8) * 253 + tp] = fmaxf(hsum2(accH[it]) * sH + BH, 0.f);
            }
        }
    }
    __syncthreads();

    for (int j = tid; j < 16 * 248; j += 256) {
        int c = j / 248, jj = j % 248;
        const float* hr = &sm[H2_O + c * 253 + jj];
        sm[U2_O + c * 248 + jj] = 0.25f * (hr[0] + hr[1] + hr[2] + hr[3]);
    }
    __syncthreads();

    // conv3 + pe, write bf16 (n,t,c), pre-scaled by dinv[n]
    {
        const int q = tid & 15, tpq = tid >> 4;
        u64b accL[4], accH[4];
#pragma unroll
        for (int it = 0; it < 4; it++) { accL[it] = 0; accH[it] = 0; }
#pragma unroll
        for (int ci = 0; ci < 16; ci++) {
            union WU { float4 v; u64b p[2]; } wv[4];
#pragma unroll
            for (int m = 0; m < 4; m++)
                wv[m].v = *(const float4*)&sm[W3K_O + 4 * ((ci * 4 + m) * 16 + q)];
#pragma unroll
            for (int it = 0; it < 4; it++) {
                int tp = tpq + 16 * it;
                if (tp < 61) {
                    union UB { float4 v[2]; u64b p[4]; } ub;
                    const float4* up = (const float4*)&sm[U2_O + ci * 248 + 4 * tp];
                    ub.v[0] = up[0]; ub.v[1] = up[1];
#pragma unroll
                    for (int m = 0; m < 4; m++) {
                        fma2(accL[it], wv[m].p[0], ub.p[m]);
                        fma2(accH[it], wv[m].p[1], ub.p[m]);
                    }
                }
            }
        }
        float sL = sm[S3_O + q], BL = sm[B3_O + q], peL = sm[PE_O + q];
        float sH = sm[S3_O + q + 16], BH = sm[B3_O + q + 16], peH = sm[PE_O + q + 16];
#pragma unroll
        for (int it = 0; it < 4; it++) {
            int tp = tpq + 16 * it;
            if (tp < 61) {
                size_t base = ((size_t)n * 61 + tp) * 32;
                out[base + q]      = __float2bfloat16((fmaxf(hsum2(accL[it]) * sL + BL, 0.f) + peL) * dvn);
                out[base + q + 16] = __float2bfloat16((fmaxf(hsum2(accH[it]) * sH + BH, 0.f) + peH) * dvn);
            }
        }
    }
}

// ---------------- fused GCN layer: pipelined gather + bf16 wmma GEMM ----------------
// Input h is pre-scaled by dinv[src]; gather is a pure sum.
// One block = 2 nodes = 122 rows (padded to 128).
// DO_CONTRIB=false: write relu((s@W)*dinv+b)*dinv to out (bf16, pre-scaled for next layer).
// DO_CONTRIB=true : compute per-node dense contribs in-block, write g_contrib only.
template <int K, bool DO_CONTRIB>
__global__ __launch_bounds__(256, 2) void gcn_fused_kernel(
    const __nv_bfloat16* __restrict__ h, const float* __restrict__ W,
    const float* __restrict__ bias, __nv_bfloat16* __restrict__ out,
    const float* __restrict__ dw)
{
    constexpr int LDA = K + 8;
    constexpr int LDW = 136;
    constexpr int LDC = 132;
    constexpr int V8 = TP2 * K / 8;          // 244 (K=32) / 976 (K=128)
    constexpr int VPT = (V8 + 255) / 256;    // 1 / 4
    extern __shared__ char sgc[];
    __nv_bfloat16* ws = (__nv_bfloat16*)sgc;   // K * LDW
    __nv_bfloat16* as = ws + K * LDW;           // 128 * LDA
    float* cs = (float*)sgc;                    // reuse for C tile (128 * LDC f32)
    __shared__ float bs[128];
    __shared__ float red[8][4];

    const int tid = threadIdx.x;
    const int bid = blockIdx.x;

    if (tid < 128) bs[tid] = bias[tid];
    for (int i = tid; i < K * 32; i += 256) {
        int k = i >> 5, c4 = i & 31;
        float4 v = *(const float4*)&W[k * 128 + c4 * 4];
        __nv_bfloat16* p = &ws[k * LDW + c4 * 4];
        p[0] = __float2bfloat16(v.x); p[1] = __float2bfloat16(v.y);
        p[2] = __float2bfloat16(v.z); p[3] = __float2bfloat16(v.w);
    }
    // zero pad rows 122..127 of A
    for (int i = tid; i < 6 * (K / 8); i += 256) {
        int r = 122 + i / (K / 8), c8 = i % (K / 8);
        *(uint4*)&as[r * LDA + c8 * 8] = make_uint4(0, 0, 0, 0);
    }

    // gather: sum pre-scaled rows of self + neighbors, 2-way edge unroll
#pragma unroll 1
    for (int nh = 0; nh < 2; nh++) {
        const int n = 2 * bid + nh;
        const uint4* hn = (const uint4*)(h + (size_t)n * (TP2 * K));
        u64b accp[VPT][4];
#pragma unroll
        for (int v = 0; v < VPT; v++) {
            int i = tid + v * 256;
            if (i < V8) {
                uint4 b = hn[i];
                accp[v][0] = expand_bf2(b.x);
                accp[v][1] = expand_bf2(b.y);
                accp[v][2] = expand_bf2(b.z);
                accp[v][3] = expand_bf2(b.w);
            }
        }
        const int jb = g_off[n], je = g_off[n + 1];
        int e = jb;
        for (; e + 2 <= je; e += 2) {
            const uint4* p0 = (const uint4*)(h + (size_t)g_col[e]     * (TP2 * K));
            const uint4* p1 = (const uint4*)(h + (size_t)g_col[e + 1] * (TP2 * K));
            uint4 b0[VPT], b1[VPT];
#pragma unroll
            for (int v = 0; v < VPT; v++) {
                int i = tid + v * 256;
                if (i < V8) { b0[v] = p0[i]; b1[v] = p1[i]; }
            }
#pragma unroll
            for (int v = 0; v < VPT; v++) {
                int i = tid + v * 256;
                if (i < V8) { acc_u4(accp[v], b0[v]); acc_u4(accp[v], b1[v]); }
            }
        }
        if (e < je) {
            const uint4* p0 = (const uint4*)(h + (size_t)g_col[e] * (TP2 * K));
#pragma unroll
            for (int v = 0; v < VPT; v++) {
                int i = tid + v * 256;
                if (i < V8) acc_u4(accp[v], p0[i]);
            }
        }
#pragma unroll
        for (int v = 0; v < VPT; v++) {
            int i = tid + v * 256;
            if (i < V8) {
                int r = nh * TP2 + i / (K / 8), c8 = i % (K / 8);
                uint4 o;
                o.x = pair_to_bf2(accp[v][0]);
                o.y = pair_to_bf2(accp[v][1]);
                o.z = pair_to_bf2(accp[v][2]);
                o.w = pair_to_bf2(accp[v][3]);
                *(uint4*)&as[r * LDA + c8 * 8] = o;
            }
        }
    }
    __syncthreads();

    // wmma: 8 warps (4 row x 2 col), warp tile 32x64
    const int wid = tid >> 5;
    const int wr = wid & 3;
    const int wc = wid >> 2;
    wmma::fragment<wmma::accumulator, 16, 16, 16, float> cf[2][4];
#pragma unroll
    for (int i = 0; i < 2; i++)
#pragma unroll
        for (int j = 0; j < 4; j++) wmma::fill_fragment(cf[i][j], 0.f);

#pragma unroll
    for (int k0 = 0; k0 < K; k0 += 16) {
        wmma::fragment<wmma::matrix_a, 16, 16, 16, __nv_bfloat16, wmma::row_major> af[2];
#pragma unroll
        for (int i = 0; i < 2; i++)
            wmma::load_matrix_sync(af[i], as + (wr * 32 + i * 16) * LDA + k0, LDA);
        wmma::fragment<wmma::matrix_b, 16, 16, 16, __nv_bfloat16, wmma::row_major> bf[4];
#pragma unroll
        for (int j = 0; j < 4; j++)
            wmma::load_matrix_sync(bf[j], ws + k0 * LDW + wc * 64 + j * 16, LDW);
#pragma unroll
        for (int i = 0; i < 2; i++)
#pragma unroll
            for (int j = 0; j < 4; j++)
                wmma::mma_sync(cf[i][j], af[i], bf[j], cf[i][j]);
    }
    __syncthreads();   // input tiles dead; reuse as C
#pragma unroll
    for (int i = 0; i < 2; i++)
#pragma unroll
        for (int j = 0; j < 4; j++)
            wmma::store_matrix_sync(cs + (wr * 32 + i * 16) * LDC + wc * 64 + j * 16,
                                    cf[i][j], LDC, wmma::mem_row_major);
    __syncthreads();

    if (!DO_CONTRIB) {
        // epilogue: relu((c*dinv)+bias) * dinv (pre-scale for next layer's gather)
        for (int idx = tid; idx < 128 * 64; idx += 256) {
            int r = idx >> 6, c2 = idx & 63;
            if (r < 122) {
                int nh = (r >= TP2) ? 1 : 0;
                int n = 2 * bid + nh;
                int t = r - TP2 * nh;
                float dv = g_dinv[n];
                float v0 = fmaxf(cs[r * LDC + 2 * c2]     * dv + bs[2 * c2], 0.f) * dv;
                float v1 = fmaxf(cs[r * LDC + 2 * c2 + 1] * dv + bs[2 * c2 + 1], 0.f) * dv;
                ((__nv_bfloat162*)out)[(size_t)(n * TP2 + t) * 64 + c2] =
                    __floats2bfloat162_rn(v0, v1);
            }
        }
    } else {
        // fused contrib: per-node dot with dense weights, deterministic reduce
        const int half = tid >> 7, d = tid & 127;
        const int n = 2 * bid + half;
        const float dv = g_dinv[n];
        const float bsv = bs[d];
        float a0 = 0.f, a1 = 0.f, a2 = 0.f, a3 = 0.f;
#pragma unroll 4
        for (int t = 0; t < TP2; t++) {
            float v = fmaxf(cs[(half * TP2 + t) * LDC + d] * dv + bsv, 0.f);
            const float4 w = *(const float4*)&dw[(size_t)(d * TP2 + t) * 4];
            a0 += v * w.x; a1 += v * w.y; a2 += v * w.z; a3 += v * w.w;
        }
#pragma unroll
        for (int o = 16; o > 0; o >>= 1) {
            a0 += __shfl_down_sync(0xffffffff, a0, o);
            a1 += __shfl_down_sync(0xffffffff, a1, o);
            a2 += __shfl_down_sync(0xffffffff, a2, o);
            a3 += __shfl_down_sync(0xffffffff, a3, o);
        }
        const int wid2 = tid >> 5;
        if ((tid & 31) == 0) {
            red[wid2][0] = a0; red[wid2][1] = a1; red[wid2][2] = a2; red[wid2][3] = a3;
        }
        __syncthreads();
        if (tid < 8) {
            int hh = tid >> 2, j = tid & 3;
            float s = red[hh * 4 + 0][j] + red[hh * 4 + 1][j]
                    + red[hh * 4 + 2][j] + red[hh * 4 + 3][j];
            g_contrib[(2 * bid + hh) * 4 + j] = s;
        }
    }
}

// ---------------- batch pooling + bias + log_softmax ----------------
__global__ __launch_bounds__(256) void final_kernel(
    const int* __restrict__ batch, const float* __restrict__ db,
    float* __restrict__ out)
{
    const int b = blockIdx.x, tid = threadIdx.x;
    float a0 = 0.f, a1 = 0.f, a2 = 0.f, a3 = 0.f;
    int c = 0;
    for (int n = tid; n < NN; n += 256) {
        if (batch[n] == b) {
            const float4 v = *(const float4*)&g_contrib[n * 4];
            a0 += v.x; a1 += v.y; a2 += v.z; a3 += v.w;
            c++;
        }
    }
    __shared__ float r0[256], r1[256], r2[256], r3[256];
    __shared__ int rc[256];
    r0[tid] = a0; r1[tid] = a1; r2[tid] = a2; r3[tid] = a3; rc[tid] = c;
    __syncthreads();
    for (int s = 128; s > 0; s >>= 1) {
        if (tid < s) {
            r0[tid] += r0[tid + s]; r1[tid] += r1[tid + s];
            r2[tid] += r2[tid + s]; r3[tid] += r3[tid + s];
            rc[tid] += rc[tid + s];
        }
        __syncthreads();
    }
    if (tid == 0) {
        float cc = fmaxf((float)rc[0], 1.f);
        float l0 = r0[0] / cc + db[0];
        float l1 = r1[0] / cc + db[1];
        float l2 = r2[0] / cc + db[2];
        float l3 = r3[0] / cc + db[3];
        float m = fmaxf(fmaxf(l0, l1), fmaxf(l2, l3));
        float sum = expf(l0 - m) + expf(l1 - m) + expf(l2 - m) + expf(l3 - m);
        float ls = logf(sum);
        out[b * 4 + 0] = l0 - m - ls;
        out[b * 4 + 1] = l1 - m - ls;
        out[b * 4 + 2] = l2 - m - ls;
        out[b * 4 + 3] = l3 - m - ls;
    }
}

// ---------------- launch ----------------
extern "C" void kernel_launch(void* const* d_in, const int* in_sizes, int n_in,
                              void* d_out, int out_size)
{
    const float* x   = (const float*)d_in[0];
    const float* pos = (const float*)d_in[1];
    const float* c1w = (const float*)d_in[2];
    const float* c1b = (const float*)d_in[3];
    const float* bg1 = (const float*)d_in[4];
    const float* bb1 = (const float*)d_in[5];
    const float* c2w = (const float*)d_in[6];
    const float* c2b = (const float*)d_in[7];
    const float* bg2 = (const float*)d_in[8];
    const float* bb2 = (const float*)d_in[9];
    const float* c3w = (const float*)d_in[10];
    const float* c3b = (const float*)d_in[11];
    const float* bg3 = (const float*)d_in[12];
    const float* bb3 = (const float*)d_in[13];
    const float* pw1 = (const float*)d_in[14];
    const float* pb1 = (const float*)d_in[15];
    const float* pw2 = (const float*)d_in[16];
    const float* pb2 = (const float*)d_in[17];
    const float* gw1 = (const float*)d_in[18];
    const float* gb1 = (const float*)d_in[19];
    const float* gw2 = (const float*)d_in[20];
    const float* gb2 = (const float*)d_in[21];
    const float* dw  = (const float*)d_in[22];
    const float* db  = (const float*)d_in[23];
    const int*   ei  = (const int*)d_in[24];
    const int*   bat = (const int*)d_in[25];
    float* out = (float*)d_out;

    const int g1_smem = 128 * 132 * 4;                    // 67584 (C tile dominates)
    const int g2_smem = (128 * 136 + 128 * 136) * 2;      // 69632

    cudaFuncSetAttribute(conv_kernel, cudaFuncAttributeMaxDynamicSharedMemorySize, CONV_SMEM_BYTES);
    cudaFuncSetAttribute(gcn_fused_kernel<32, false>,  cudaFuncAttributeMaxDynamicSharedMemorySize, g1_smem);
    cudaFuncSetAttribute(gcn_fused_kernel<128, true>,  cudaFuncAttributeMaxDynamicSharedMemorySize, g2_smem);

    __nv_bfloat16 *h0, *h1;
    cudaGetSymbolAddress((void**)&h0, g_h0);
    cudaGetSymbolAddress((void**)&h1, g_h1);

    prep_kernel<<<1, 1024>>>(ei);

    conv_kernel<<<NN, 256, CONV_SMEM_BYTES>>>(
        x, pos, c1w, c1b, bg1, bb1, c2w, c2b, bg2, bb2,
        c3w, c3b, bg3, bb3, pw1, pb1, pw2, pb2, h0);

    gcn_fused_kernel<32, false><<<NN / 2, 256, g1_smem>>>(h0, gw1, gb1, h1, nullptr);
    gcn_fused_kernel<128, true><<<NN / 2, 256, g2_smem>>>(h1, gw2, gb2, nullptr, dw);

    final_kernel<<<BBATCH, 256>>>(bat, db, out);
}